// round 1
// baseline (speedup 1.0000x reference)
#include <cuda_runtime.h>
#include <math.h>

#define BATCH 4
#define CDIM  256
#define CHALF 128
#define NPIX  4096

#define BM 128
#define BN 128
#define BK 16
#define TM 8
#define TN 8
#define NTHREADS 256

// ---- scratch (device globals; no dynamic allocation allowed) ----
__device__ float d_theta[BATCH * CHALF * NPIX];            // [b][c][i]
__device__ float d_phi  [BATCH * CHALF * NPIX];            // [b][c][j]
__device__ float d_g    [BATCH * CHALF * NPIX];            // [b][c][j]
__device__ float d_gst  [BATCH * NPIX  * CHALF];           // [b][j][c] = g/den
__device__ float d_y    [BATCH * CHALF * NPIX];            // [b][c][i]
__device__ float d_den  [BATCH * NPIX];                    // [b][j]
__device__ float d_denp [BATCH * 32 * NPIX];               // per-i-tile partial column sums
__device__ float d_E    [(size_t)BATCH * NPIX * NPIX];     // exp(scores), 256 MB

// ============================================================
// Kernel 1: theta/phi/g projections.
// One 128-row weight matrix per blockIdx.y (0:w1,1:w2,2:w3).
// C[m,n] = sum_k W[m,k] * x[b,k,n]  (K=256)
// ============================================================
__global__ __launch_bounds__(NTHREADS) void proj_kernel(
    const float* __restrict__ x,
    const float* __restrict__ w1, const float* __restrict__ b1,
    const float* __restrict__ w2, const float* __restrict__ b2,
    const float* __restrict__ w3, const float* __restrict__ b3)
{
    __shared__ float As[BK][BM + 4];
    __shared__ float Bs[BK][BN];

    const int n0  = blockIdx.x * BN;
    const int sel = blockIdx.y;
    const int b   = blockIdx.z;
    const int tid = threadIdx.x;
    const int tx  = tid & 15, ty = tid >> 4;

    const float* W  = (sel == 0) ? w1 : (sel == 1) ? w2 : w3;
    const float* Bv = (sel == 0) ? b1 : (sel == 1) ? b2 : b3;
    float*       O  = (sel == 0) ? d_theta : (sel == 1) ? d_phi : d_g;

    const float* xb = x + (size_t)b * CDIM * NPIX;

    float acc[TM][TN];
#pragma unroll
    for (int i = 0; i < TM; ++i)
#pragma unroll
        for (int j = 0; j < TN; ++j) acc[i][j] = 0.f;

    for (int k0 = 0; k0 < CDIM; k0 += BK) {
#pragma unroll
        for (int e = 0; e < (BK * BM) / NTHREADS; ++e) {   // W[m][k], k fast
            int idx = e * NTHREADS + tid;
            int k = idx & (BK - 1), m = idx >> 4;
            As[k][m] = W[m * CDIM + k0 + k];
        }
#pragma unroll
        for (int e = 0; e < (BK * BN) / NTHREADS; ++e) {   // x[k][n], n fast
            int idx = e * NTHREADS + tid;
            int n = idx & (BN - 1), k = idx >> 7;
            Bs[k][n] = xb[(size_t)(k0 + k) * NPIX + n0 + n];
        }
        __syncthreads();
#pragma unroll
        for (int k = 0; k < BK; ++k) {
            float a[TM], bb[TN];
            *(float4*)&a[0]  = *(const float4*)&As[k][ty * TM];
            *(float4*)&a[4]  = *(const float4*)&As[k][ty * TM + 4];
            *(float4*)&bb[0] = *(const float4*)&Bs[k][tx * TN];
            *(float4*)&bb[4] = *(const float4*)&Bs[k][tx * TN + 4];
#pragma unroll
            for (int i = 0; i < TM; ++i)
#pragma unroll
                for (int j = 0; j < TN; ++j) acc[i][j] += a[i] * bb[j];
        }
        __syncthreads();
    }

#pragma unroll
    for (int i = 0; i < TM; ++i) {
        int m = ty * TM + i;
        float bias = Bv[m];
        float* dst = O + ((size_t)b * CHALF + m) * NPIX + n0 + tx * TN;
        *(float4*)&dst[0] = make_float4(acc[i][0] + bias, acc[i][1] + bias,
                                        acc[i][2] + bias, acc[i][3] + bias);
        *(float4*)&dst[4] = make_float4(acc[i][4] + bias, acc[i][5] + bias,
                                        acc[i][6] + bias, acc[i][7] + bias);
    }
}

// ============================================================
// Kernel 2: E[i,j] = exp(sum_c theta[c,i]*phi[c,j]); per-i-tile column sums.
// K = 128.
// ============================================================
__global__ __launch_bounds__(NTHREADS) void scores_kernel()
{
    __shared__ float As[BK][BM + 4];
    __shared__ float Bs[BK][BN];
    __shared__ float red[16][BN];

    const int j0 = blockIdx.x * BN;
    const int i0 = blockIdx.y * BM;
    const int b  = blockIdx.z;
    const int tid = threadIdx.x;
    const int tx = tid & 15, ty = tid >> 4;

    const float* th = d_theta + (size_t)b * CHALF * NPIX;
    const float* ph = d_phi   + (size_t)b * CHALF * NPIX;

    float acc[TM][TN];
#pragma unroll
    for (int i = 0; i < TM; ++i)
#pragma unroll
        for (int j = 0; j < TN; ++j) acc[i][j] = 0.f;

    for (int k0 = 0; k0 < CHALF; k0 += BK) {
#pragma unroll
        for (int e = 0; e < 8; ++e) {                      // theta[k][i], i(m) fast
            int idx = e * NTHREADS + tid;
            int m = idx & 127, k = idx >> 7;
            As[k][m] = th[(size_t)(k0 + k) * NPIX + i0 + m];
        }
#pragma unroll
        for (int e = 0; e < 8; ++e) {                      // phi[k][j], j(n) fast
            int idx = e * NTHREADS + tid;
            int n = idx & 127, k = idx >> 7;
            Bs[k][n] = ph[(size_t)(k0 + k) * NPIX + j0 + n];
        }
        __syncthreads();
#pragma unroll
        for (int k = 0; k < BK; ++k) {
            float a[TM], bb[TN];
            *(float4*)&a[0]  = *(const float4*)&As[k][ty * TM];
            *(float4*)&a[4]  = *(const float4*)&As[k][ty * TM + 4];
            *(float4*)&bb[0] = *(const float4*)&Bs[k][tx * TN];
            *(float4*)&bb[4] = *(const float4*)&Bs[k][tx * TN + 4];
#pragma unroll
            for (int i = 0; i < TM; ++i)
#pragma unroll
                for (int j = 0; j < TN; ++j) acc[i][j] += a[i] * bb[j];
        }
        __syncthreads();
    }

    float csum[TN];
#pragma unroll
    for (int j = 0; j < TN; ++j) csum[j] = 0.f;

    float* Eb = d_E + (size_t)b * NPIX * NPIX;
#pragma unroll
    for (int i = 0; i < TM; ++i) {
        int gi = i0 + ty * TM + i;
        float ev[TN];
#pragma unroll
        for (int j = 0; j < TN; ++j) { ev[j] = expf(acc[i][j]); csum[j] += ev[j]; }
        float* dst = Eb + (size_t)gi * NPIX + j0 + tx * TN;
        *(float4*)&dst[0] = make_float4(ev[0], ev[1], ev[2], ev[3]);
        *(float4*)&dst[4] = make_float4(ev[4], ev[5], ev[6], ev[7]);
    }

#pragma unroll
    for (int j = 0; j < TN; ++j) red[ty][tx * TN + j] = csum[j];
    __syncthreads();
    if (tid < BN) {
        float s = 0.f;
#pragma unroll
        for (int r = 0; r < 16; ++r) s += red[r][tid];
        d_denp[((size_t)b * 32 + blockIdx.y) * NPIX + j0 + tid] = s;  // deterministic (no atomics)
    }
}

// ============================================================
// Kernel 3: den[b,j] = sum over 32 i-tile partials (deterministic)
// ============================================================
__global__ void den_reduce_kernel()
{
    int j = blockIdx.x * 256 + threadIdx.x;
    int b = blockIdx.y;
    float s = 0.f;
#pragma unroll
    for (int t = 0; t < 32; ++t) s += d_denp[((size_t)b * 32 + t) * NPIX + j];
    d_den[b * NPIX + j] = s;
}

// ============================================================
// Kernel 4: gst[b,j,c] = g[b,c,j] / den[b,j]  (32x32 smem transpose)
// ============================================================
__global__ void gscale_kernel()
{
    __shared__ float t[32][33];
    const int j0 = blockIdx.x * 32;
    const int c0 = blockIdx.y * 32;
    const int b  = blockIdx.z;
    const float* gb = d_g + (size_t)b * CHALF * NPIX;

    for (int r = threadIdx.y; r < 32; r += 8)
        t[r][threadIdx.x] = gb[(size_t)(c0 + r) * NPIX + j0 + threadIdx.x];
    __syncthreads();

    float* go = d_gst + (size_t)b * NPIX * CHALF;
    const float* den = d_den + b * NPIX;
    for (int r = threadIdx.y; r < 32; r += 8) {
        int j = j0 + r;
        go[(size_t)j * CHALF + c0 + threadIdx.x] = t[threadIdx.x][r] / den[j];
    }
}

// ============================================================
// Kernel 5: y[b,c,i] = sum_j E[i,j] * gst[j,c].  K = 4096.
// m(=i) mapped to tx so y writes are float4/contiguous in i.
// ============================================================
__global__ __launch_bounds__(NTHREADS) void y_kernel()
{
    __shared__ float As[BK][BM + 4];
    __shared__ float Bs[BK][BN];

    const int i0 = blockIdx.x * BM;
    const int b  = blockIdx.z;
    const int tid = threadIdx.x;
    const int tx = tid & 15, ty = tid >> 4;

    const float* Eb = d_E   + (size_t)b * NPIX * NPIX;
    const float* G  = d_gst + (size_t)b * NPIX * CHALF;

    float acc[TM][TN];
#pragma unroll
    for (int i = 0; i < TM; ++i)
#pragma unroll
        for (int j = 0; j < TN; ++j) acc[i][j] = 0.f;

    for (int k0 = 0; k0 < NPIX; k0 += BK) {
#pragma unroll
        for (int e = 0; e < 8; ++e) {                      // E[i][k], k fast -> transposed store
            int idx = e * NTHREADS + tid;
            int k = idx & 15, m = idx >> 4;
            As[k][m] = Eb[(size_t)(i0 + m) * NPIX + k0 + k];
        }
#pragma unroll
        for (int e = 0; e < 8; ++e) {                      // gst[k][c], c(n) fast
            int idx = e * NTHREADS + tid;
            int n = idx & 127, k = idx >> 7;
            Bs[k][n] = G[(size_t)(k0 + k) * CHALF + n];
        }
        __syncthreads();
#pragma unroll
        for (int k = 0; k < BK; ++k) {
            float a[TM], bb[TN];
            *(float4*)&a[0]  = *(const float4*)&As[k][tx * TM];     // i along tx
            *(float4*)&a[4]  = *(const float4*)&As[k][tx * TM + 4];
            *(float4*)&bb[0] = *(const float4*)&Bs[k][ty * TN];     // c along ty
            *(float4*)&bb[4] = *(const float4*)&Bs[k][ty * TN + 4];
#pragma unroll
            for (int i = 0; i < TM; ++i)
#pragma unroll
                for (int j = 0; j < TN; ++j) acc[i][j] += a[i] * bb[j];
        }
        __syncthreads();
    }

    float* yb = d_y + (size_t)b * CHALF * NPIX;
#pragma unroll
    for (int j = 0; j < TN; ++j) {
        int c = ty * TN + j;
        float* dst = yb + (size_t)c * NPIX + i0 + tx * TM;
        *(float4*)&dst[0] = make_float4(acc[0][j], acc[1][j], acc[2][j], acc[3][j]);
        *(float4*)&dst[4] = make_float4(acc[4][j], acc[5][j], acc[6][j], acc[7][j]);
    }
}

// ============================================================
// Kernel 6: out[b,o,i] = sum_c w4[o,c]*y[b,c,i] + b4[o] + x[b,o,i]
// ============================================================
__global__ __launch_bounds__(NTHREADS) void out_kernel(
    const float* __restrict__ x, const float* __restrict__ w4,
    const float* __restrict__ b4, float* __restrict__ out)
{
    __shared__ float As[BK][BM + 4];
    __shared__ float Bs[BK][BN];

    const int n0 = blockIdx.x * BN;
    const int m0 = blockIdx.y * BM;
    const int b  = blockIdx.z;
    const int tid = threadIdx.x;
    const int tx = tid & 15, ty = tid >> 4;

    const float* yb = d_y + (size_t)b * CHALF * NPIX;

    float acc[TM][TN];
#pragma unroll
    for (int i = 0; i < TM; ++i)
#pragma unroll
        for (int j = 0; j < TN; ++j) acc[i][j] = 0.f;

    for (int k0 = 0; k0 < CHALF; k0 += BK) {
#pragma unroll
        for (int e = 0; e < 8; ++e) {                      // w4[m][k], k fast
            int idx = e * NTHREADS + tid;
            int k = idx & 15, m = idx >> 4;
            As[k][m] = w4[(m0 + m) * CHALF + k0 + k];
        }
#pragma unroll
        for (int e = 0; e < 8; ++e) {                      // y[k][n], n fast
            int idx = e * NTHREADS + tid;
            int n = idx & 127, k = idx >> 7;
            Bs[k][n] = yb[(size_t)(k0 + k) * NPIX + n0 + n];
        }
        __syncthreads();
#pragma unroll
        for (int k = 0; k < BK; ++k) {
            float a[TM], bb[TN];
            *(float4*)&a[0]  = *(const float4*)&As[k][ty * TM];
            *(float4*)&a[4]  = *(const float4*)&As[k][ty * TM + 4];
            *(float4*)&bb[0] = *(const float4*)&Bs[k][tx * TN];
            *(float4*)&bb[4] = *(const float4*)&Bs[k][tx * TN + 4];
#pragma unroll
            for (int i = 0; i < TM; ++i)
#pragma unroll
                for (int j = 0; j < TN; ++j) acc[i][j] += a[i] * bb[j];
        }
        __syncthreads();
    }

#pragma unroll
    for (int i = 0; i < TM; ++i) {
        int gm = m0 + ty * TM + i;
        float bias = b4[gm];
        size_t off = ((size_t)b * CDIM + gm) * NPIX + n0 + tx * TN;
        float4 x0 = *(const float4*)&x[off];
        float4 x1 = *(const float4*)&x[off + 4];
        float* dst = out + off;
        *(float4*)&dst[0] = make_float4(acc[i][0] + bias + x0.x, acc[i][1] + bias + x0.y,
                                        acc[i][2] + bias + x0.z, acc[i][3] + bias + x0.w);
        *(float4*)&dst[4] = make_float4(acc[i][4] + bias + x1.x, acc[i][5] + bias + x1.y,
                                        acc[i][6] + bias + x1.z, acc[i][7] + bias + x1.w);
    }
}

// ============================================================
extern "C" void kernel_launch(void* const* d_in, const int* in_sizes, int n_in,
                              void* d_out, int out_size)
{
    const float* x  = (const float*)d_in[0];
    const float* w1 = (const float*)d_in[1];
    const float* b1 = (const float*)d_in[2];
    const float* w2 = (const float*)d_in[3];
    const float* b2 = (const float*)d_in[4];
    const float* w3 = (const float*)d_in[5];
    const float* b3 = (const float*)d_in[6];
    const float* w4 = (const float*)d_in[7];
    const float* b4 = (const float*)d_in[8];
    float* out = (float*)d_out;

    proj_kernel   <<<dim3(NPIX / BN, 3, BATCH), NTHREADS>>>(x, w1, b1, w2, b2, w3, b3);
    scores_kernel <<<dim3(NPIX / BN, NPIX / BM, BATCH), NTHREADS>>>();
    den_reduce_kernel<<<dim3(NPIX / 256, BATCH), 256>>>();
    gscale_kernel <<<dim3(NPIX / 32, CHALF / 32, BATCH), dim3(32, 8)>>>();
    y_kernel      <<<dim3(NPIX / BM, 1, BATCH), NTHREADS>>>();
    out_kernel    <<<dim3(NPIX / BN, CDIM / BM, BATCH), NTHREADS>>>(x, w4, b4, out);
}

// round 4
// speedup vs baseline: 3.6246x; 3.6246x over previous
#include <cuda_runtime.h>
#include <cuda_bf16.h>
#include <math.h>
#include <stdint.h>

#define BATCH 4
#define CDIM  256
#define CHALF 128
#define NPIX  4096

#define BM 128
#define BN 128
#define BK 16
#define TM 8
#define TN 8
#define NTHREADS 256

// ---- scratch (device globals; no dynamic allocation allowed) ----
__device__ __nv_bfloat16 d_thT[BATCH * NPIX * CHALF];        // theta^T [b][i][c] bf16
__device__ __nv_bfloat16 d_phT[BATCH * NPIX * CHALF];        // phi^T   [b][j][c] bf16
__device__ float         d_g  [BATCH * CHALF * NPIX];        // g [b][c][j] fp32
__device__ __nv_bfloat16 d_gb [BATCH * CHALF * NPIX];        // g/den [b][c][j] bf16
__device__ float         d_y  [BATCH * CHALF * NPIX];        // y [b][c][i] fp32
__device__ float         d_den [BATCH * NPIX];
__device__ float         d_denp[BATCH * 16 * NPIX];
__device__ __nv_bfloat16 d_E  [(size_t)BATCH * NPIX * NPIX]; // exp(scores) bf16, 128 MB

// ================= helpers =================
__device__ __forceinline__ uint32_t smem_u32(const void* p) {
    uint32_t a;
    asm("{ .reg .u64 t; cvta.to.shared.u64 t, %1; cvt.u32.u64 %0, t; }" : "=r"(a) : "l"(p));
    return a;
}
__device__ __forceinline__ uint32_t pack_bf16x2(float lo, float hi) {
    uint32_t r;
    asm("cvt.rn.bf16x2.f32 %0, %1, %2;" : "=r"(r) : "f"(hi), "f"(lo));
    return r;
}
__device__ __forceinline__ void ldm_x4(uint32_t& r0, uint32_t& r1, uint32_t& r2, uint32_t& r3,
                                       uint32_t addr) {
    asm volatile("ldmatrix.sync.aligned.m8n8.x4.shared.b16 {%0,%1,%2,%3}, [%4];"
                 : "=r"(r0), "=r"(r1), "=r"(r2), "=r"(r3) : "r"(addr));
}
__device__ __forceinline__ void mma_bf16(float* c, const uint32_t* a, const uint32_t* b) {
    asm volatile(
        "mma.sync.aligned.m16n8k16.row.col.f32.bf16.bf16.f32 "
        "{%0,%1,%2,%3}, {%4,%5,%6,%7}, {%8,%9}, {%0,%1,%2,%3};"
        : "+f"(c[0]), "+f"(c[1]), "+f"(c[2]), "+f"(c[3])
        : "r"(a[0]), "r"(a[1]), "r"(a[2]), "r"(a[3]), "r"(b[0]), "r"(b[1]));
}
__device__ __forceinline__ void cp16(uint32_t dst, const void* src) {
    asm volatile("cp.async.cg.shared.global [%0], [%1], 16;" :: "r"(dst), "l"(src) : "memory");
}
__device__ __forceinline__ void cp_commit() { asm volatile("cp.async.commit_group;" ::: "memory"); }
__device__ __forceinline__ void cp_wait0()  { asm volatile("cp.async.wait_group 0;" ::: "memory"); }
__device__ __forceinline__ void cp_wait1()  { asm volatile("cp.async.wait_group 1;" ::: "memory"); }

// ============================================================
// Kernel 1: projections (fp32 SIMT). theta/phi -> bf16 [n][c]; g -> fp32 [c][n]
// ============================================================
__global__ __launch_bounds__(NTHREADS) void proj_kernel(
    const float* __restrict__ x,
    const float* __restrict__ w1, const float* __restrict__ b1,
    const float* __restrict__ w2, const float* __restrict__ b2,
    const float* __restrict__ w3, const float* __restrict__ b3)
{
    __shared__ float As[BK][BM + 4];
    __shared__ float Bs[BK][BN];

    const int n0  = blockIdx.x * BN;
    const int sel = blockIdx.y;
    const int b   = blockIdx.z;
    const int tid = threadIdx.x;
    const int tx  = tid & 15, ty = tid >> 4;

    const float* W  = (sel == 0) ? w1 : (sel == 1) ? w2 : w3;
    const float* Bv = (sel == 0) ? b1 : (sel == 1) ? b2 : b3;

    const float* xb = x + (size_t)b * CDIM * NPIX;

    float acc[TM][TN];
#pragma unroll
    for (int i = 0; i < TM; ++i)
#pragma unroll
        for (int j = 0; j < TN; ++j) acc[i][j] = 0.f;

    for (int k0 = 0; k0 < CDIM; k0 += BK) {
#pragma unroll
        for (int e = 0; e < (BK * BM) / NTHREADS; ++e) {
            int idx = e * NTHREADS + tid;
            int k = idx & (BK - 1), m = idx >> 4;
            As[k][m] = W[m * CDIM + k0 + k];
        }
#pragma unroll
        for (int e = 0; e < (BK * BN) / NTHREADS; ++e) {
            int idx = e * NTHREADS + tid;
            int n = idx & (BN - 1), k = idx >> 7;
            Bs[k][n] = xb[(size_t)(k0 + k) * NPIX + n0 + n];
        }
        __syncthreads();
#pragma unroll
        for (int k = 0; k < BK; ++k) {
            float a[TM], bb[TN];
            *(float4*)&a[0]  = *(const float4*)&As[k][ty * TM];
            *(float4*)&a[4]  = *(const float4*)&As[k][ty * TM + 4];
            *(float4*)&bb[0] = *(const float4*)&Bs[k][tx * TN];
            *(float4*)&bb[4] = *(const float4*)&Bs[k][tx * TN + 4];
#pragma unroll
            for (int i = 0; i < TM; ++i)
#pragma unroll
                for (int j = 0; j < TN; ++j) acc[i][j] += a[i] * bb[j];
        }
        __syncthreads();
    }

    if (sel < 2) {
        __nv_bfloat16* O = ((sel == 0) ? d_thT : d_phT) + (size_t)b * NPIX * CHALF;
        float bias[TM];
#pragma unroll
        for (int i = 0; i < TM; ++i) bias[i] = Bv[ty * TM + i];
#pragma unroll
        for (int j = 0; j < TN; ++j) {
            int n = n0 + tx * TN + j;
            uint4 o;
            o.x = pack_bf16x2(acc[0][j] + bias[0], acc[1][j] + bias[1]);
            o.y = pack_bf16x2(acc[2][j] + bias[2], acc[3][j] + bias[3]);
            o.z = pack_bf16x2(acc[4][j] + bias[4], acc[5][j] + bias[5]);
            o.w = pack_bf16x2(acc[6][j] + bias[6], acc[7][j] + bias[7]);
            *(uint4*)(O + (size_t)n * CHALF + ty * TM) = o;
        }
    } else {
        float* O = d_g + (size_t)b * CHALF * NPIX;
#pragma unroll
        for (int i = 0; i < TM; ++i) {
            int m = ty * TM + i;
            float bias = Bv[m];
            float* dst = O + (size_t)m * NPIX + n0 + tx * TN;
            *(float4*)&dst[0] = make_float4(acc[i][0] + bias, acc[i][1] + bias,
                                            acc[i][2] + bias, acc[i][3] + bias);
            *(float4*)&dst[4] = make_float4(acc[i][4] + bias, acc[i][5] + bias,
                                            acc[i][6] + bias, acc[i][7] + bias);
        }
    }
}

// ============================================================
// Kernel 2: scores via mma.sync bf16. CTA tile 128(i) x 128(j), K=128.
// E[i,j] = exp(theta_i . phi_j) -> bf16.
// ============================================================
#define SROW 272   // bytes per smem row (128 bf16 -> 256B + 16B pad)

__global__ __launch_bounds__(256) void scores_mma_kernel()
{
    extern __shared__ __align__(16) char smem[];
    char* Asm = smem;              // 128 * 272 = 34816
    char* Bsm = smem + 34816;      // 128 * 272
    const uint32_t Asb = smem_u32(Asm), Bsb = smem_u32(Bsm);

    const int tid = threadIdx.x, wid = tid >> 5, lane = tid & 31;
    const int j0 = blockIdx.x * 128, i0 = blockIdx.y * 128, b = blockIdx.z;

    const __nv_bfloat16* Ath = d_thT + ((size_t)b * NPIX + i0) * CHALF;
    const __nv_bfloat16* Bph = d_phT + ((size_t)b * NPIX + j0) * CHALF;

#pragma unroll
    for (int e = 0; e < 8; ++e) {
        int idx = e * 256 + tid;
        int row = idx >> 4, kb = idx & 15;
        *(uint4*)(Asm + row * SROW + kb * 16) = *(const uint4*)(Ath + (size_t)row * CHALF + kb * 8);
        *(uint4*)(Bsm + row * SROW + kb * 16) = *(const uint4*)(Bph + (size_t)row * CHALF + kb * 8);
    }
    __syncthreads();

    const int wm = (wid & 3) * 32;   // warp m offset
    const int wn = (wid >> 2) * 64;  // warp n offset
    const int id = lane >> 3, l7 = lane & 7;

    float acc[2][8][4];
#pragma unroll
    for (int am = 0; am < 2; ++am)
#pragma unroll
        for (int an = 0; an < 8; ++an)
#pragma unroll
            for (int q = 0; q < 4; ++q) acc[am][an][q] = 0.f;

#pragma unroll
    for (int ks = 0; ks < 8; ++ks) {
        uint32_t a[2][4];
#pragma unroll
        for (int am = 0; am < 2; ++am) {
            uint32_t addr = Asb + (uint32_t)(wm + am * 16 + (id & 1) * 8 + l7) * SROW
                          + (uint32_t)(ks * 16 + (id >> 1) * 8) * 2;
            ldm_x4(a[am][0], a[am][1], a[am][2], a[am][3], addr);
        }
        uint32_t bf[8][2];
#pragma unroll
        for (int p = 0; p < 4; ++p) {
            uint32_t r0, r1, r2, r3;
            uint32_t addr = Bsb + (uint32_t)(wn + p * 16 + (id >> 1) * 8 + l7) * SROW
                          + (uint32_t)(ks * 16 + (id & 1) * 8) * 2;
            ldm_x4(r0, r1, r2, r3, addr);
            bf[p * 2][0] = r0; bf[p * 2][1] = r1;
            bf[p * 2 + 1][0] = r2; bf[p * 2 + 1][1] = r3;
        }
#pragma unroll
        for (int am = 0; am < 2; ++am)
#pragma unroll
            for (int an = 0; an < 8; ++an)
                mma_bf16(acc[am][an], a[am], bf[an]);
    }
    __syncthreads();

    // epilogue: exp -> bf16, stage in smem, coalesced store
    char* Es = smem;
    const int gID = lane >> 2, tig = lane & 3;
#pragma unroll
    for (int am = 0; am < 2; ++am)
#pragma unroll
        for (int an = 0; an < 8; ++an) {
            int m0 = wm + am * 16, n0 = wn + an * 8 + 2 * tig;
            float e0 = __expf(acc[am][an][0]), e1 = __expf(acc[am][an][1]);
            float e2 = __expf(acc[am][an][2]), e3 = __expf(acc[am][an][3]);
            *(uint32_t*)(Es + (m0 + gID) * SROW + n0 * 2)     = pack_bf16x2(e0, e1);
            *(uint32_t*)(Es + (m0 + gID + 8) * SROW + n0 * 2) = pack_bf16x2(e2, e3);
        }
    __syncthreads();

    __nv_bfloat16* Eb = d_E + ((size_t)b * NPIX + i0) * NPIX + j0;
#pragma unroll
    for (int e = 0; e < 8; ++e) {
        int idx = e * 256 + tid;
        int row = idx >> 4, kb = idx & 15;
        *(uint4*)(Eb + (size_t)row * NPIX + kb * 8) = *(const uint4*)(Es + row * SROW + kb * 16);
    }
}

// ============================================================
// Kernel 3: den partials: sum E over 256 i-rows per block.
// grid (2 jchunk, 16 ichunk, B), 256 thr; thread handles 8 cols (2*2048 = 4096 cols)
// ============================================================
__global__ __launch_bounds__(256) void den_part_kernel()
{
    const int jc = blockIdx.x * 2048 + threadIdx.x * 8;
    const int ic = blockIdx.y * 256;
    const int b  = blockIdx.z;
    const __nv_bfloat16* Eb = d_E + ((size_t)b * NPIX + ic) * NPIX + jc;

    float s[8];
#pragma unroll
    for (int q = 0; q < 8; ++q) s[q] = 0.f;
    for (int r = 0; r < 256; ++r) {
        uint4 v = *(const uint4*)(Eb + (size_t)r * NPIX);
        const uint32_t* h = (const uint32_t*)&v;
#pragma unroll
        for (int q = 0; q < 4; ++q) {
            s[2 * q]     += __uint_as_float(h[q] << 16);
            s[2 * q + 1] += __uint_as_float(h[q] & 0xffff0000u);
        }
    }
    float* dst = d_denp + ((size_t)b * 16 + blockIdx.y) * NPIX + jc;
    *(float4*)&dst[0] = make_float4(s[0], s[1], s[2], s[3]);
    *(float4*)&dst[4] = make_float4(s[4], s[5], s[6], s[7]);
}

__global__ void den_reduce_kernel()
{
    int j = blockIdx.x * 256 + threadIdx.x;
    int b = blockIdx.y;
    float s = 0.f;
#pragma unroll
    for (int t = 0; t < 16; ++t) s += d_denp[((size_t)b * 16 + t) * NPIX + j];
    d_den[b * NPIX + j] = s;
}

// ============================================================
// Kernel 4: gb[b][c][j] = bf16(g / den[j])
// ============================================================
__global__ void gscale_kernel()
{
    int idx = blockIdx.x * 256 + threadIdx.x;
    int j  = (idx & (NPIX / 8 - 1)) * 8;
    int c  = (idx >> 9) & (CHALF - 1);
    int b  = idx >> 16;
    const float* gp = d_g + ((size_t)b * CHALF + c) * NPIX + j;
    const float* dp = d_den + b * NPIX + j;
    float4 g0 = *(const float4*)&gp[0], g1 = *(const float4*)&gp[4];
    float4 e0 = *(const float4*)&dp[0], e1 = *(const float4*)&dp[4];
    uint4 o;
    o.x = pack_bf16x2(g0.x / e0.x, g0.y / e0.y);
    o.y = pack_bf16x2(g0.z / e0.z, g0.w / e0.w);
    o.z = pack_bf16x2(g1.x / e1.x, g1.y / e1.y);
    o.w = pack_bf16x2(g1.z / e1.z, g1.w / e1.w);
    *(uint4*)(d_gb + ((size_t)b * CHALF + c) * NPIX + j) = o;
}

// ============================================================
// Kernel 5: y via mma.sync. CTA tile 128(i) x 128(c), K=4096 in 64-wide
// double-buffered cp.async chunks. y[b][c][i] fp32.
// ============================================================
#define YROW 144

__global__ __launch_bounds__(256) void y_mma_kernel()
{
    extern __shared__ __align__(16) char smem[];
    const uint32_t sb = smem_u32(smem);

    const int tid = threadIdx.x, wid = tid >> 5, lane = tid & 31;
    const int i0 = blockIdx.x * 128, b = blockIdx.y;

    const __nv_bfloat16* Ebase = d_E  + ((size_t)b * NPIX + i0) * NPIX;
    const __nv_bfloat16* Gbase = d_gb + (size_t)b * CHALF * NPIX;

    const int wm = (wid & 3) * 32;
    const int wn = (wid >> 2) * 64;
    const int id = lane >> 3, l7 = lane & 7;

    float acc[2][8][4];
#pragma unroll
    for (int am = 0; am < 2; ++am)
#pragma unroll
        for (int an = 0; an < 8; ++an)
#pragma unroll
            for (int q = 0; q < 4; ++q) acc[am][an][q] = 0.f;

    const int lrow = tid >> 1;
    const int lcol = (tid & 1) * 4;

    auto issue_chunk = [&](int c, int bufsel) {
        uint32_t Ab = sb + (uint32_t)bufsel * 36864;
        uint32_t Bb = Ab + 18432;
        size_t k0 = (size_t)c * 64;
#pragma unroll
        for (int q = 0; q < 4; ++q) {
            cp16(Ab + lrow * YROW + (lcol + q) * 16, Ebase + (size_t)lrow * NPIX + k0 + (lcol + q) * 8);
            cp16(Bb + lrow * YROW + (lcol + q) * 16, Gbase + (size_t)lrow * NPIX + k0 + (lcol + q) * 8);
        }
    };

    issue_chunk(0, 0);
    cp_commit();

    for (int c = 0; c < 64; ++c) {
        if (c + 1 < 64) {
            issue_chunk(c + 1, (c + 1) & 1);
            cp_commit();
            cp_wait1();
        } else {
            cp_wait0();
        }
        __syncthreads();

        uint32_t Ab = sb + (uint32_t)(c & 1) * 36864;
        uint32_t Bb = Ab + 18432;
#pragma unroll
        for (int ks = 0; ks < 4; ++ks) {
            uint32_t a[2][4];
#pragma unroll
            for (int am = 0; am < 2; ++am) {
                uint32_t addr = Ab + (uint32_t)(wm + am * 16 + (id & 1) * 8 + l7) * YROW
                              + (uint32_t)(ks * 16 + (id >> 1) * 8) * 2;
                ldm_x4(a[am][0], a[am][1], a[am][2], a[am][3], addr);
            }
            uint32_t bf[8][2];
#pragma unroll
            for (int p = 0; p < 4; ++p) {
                uint32_t r0, r1, r2, r3;
                uint32_t addr = Bb + (uint32_t)(wn + p * 16 + (id >> 1) * 8 + l7) * YROW
                              + (uint32_t)(ks * 16 + (id & 1) * 8) * 2;
                ldm_x4(r0, r1, r2, r3, addr);
                bf[p * 2][0] = r0; bf[p * 2][1] = r1;
                bf[p * 2 + 1][0] = r2; bf[p * 2 + 1][1] = r3;
            }
#pragma unroll
            for (int am = 0; am < 2; ++am)
#pragma unroll
                for (int an = 0; an < 8; ++an)
                    mma_bf16(acc[am][an], a[am], bf[an]);
        }
        __syncthreads();
    }

    // epilogue: stage transposed [c][i] fp32 in smem (row stride 132 floats)
    float* Ys = (float*)smem;
    const int gID = lane >> 2, tig = lane & 3;
#pragma unroll
    for (int am = 0; am < 2; ++am)
#pragma unroll
        for (int an = 0; an < 8; ++an) {
            int m0 = wm + am * 16 + gID, n0 = wn + an * 8 + 2 * tig;
            Ys[(n0)     * 132 + m0]     = acc[am][an][0];
            Ys[(n0 + 1) * 132 + m0]     = acc[am][an][1];
            Ys[(n0)     * 132 + m0 + 8] = acc[am][an][2];
            Ys[(n0 + 1) * 132 + m0 + 8] = acc[am][an][3];
        }
    __syncthreads();

    float* yb = d_y + (size_t)b * CHALF * NPIX + i0;
#pragma unroll
    for (int e = 0; e < 16; ++e) {
        int idx = e * 256 + tid;
        int row = idx >> 5, col = (idx & 31) * 4;
        *(float4*)(yb + (size_t)row * NPIX + col) = *(const float4*)(Ys + row * 132 + col);
    }
}

// ============================================================
// Kernel 6: out = w4 . y + b4 + x (fp32 SIMT)
// ============================================================
__global__ __launch_bounds__(NTHREADS) void out_kernel(
    const float* __restrict__ x, const float* __restrict__ w4,
    const float* __restrict__ b4, float* __restrict__ out)
{
    __shared__ float As[BK][BM + 4];
    __shared__ float Bs[BK][BN];

    const int n0 = blockIdx.x * BN;
    const int m0 = blockIdx.y * BM;
    const int b  = blockIdx.z;
    const int tid = threadIdx.x;
    const int tx = tid & 15, ty = tid >> 4;

    const float* yb = d_y + (size_t)b * CHALF * NPIX;

    float acc[TM][TN];
#pragma unroll
    for (int i = 0; i < TM; ++i)
#pragma unroll
        for (int j = 0; j < TN; ++j) acc[i][j] = 0.f;

    for (int k0 = 0; k0 < CHALF; k0 += BK) {
#pragma unroll
        for (int e = 0; e < 8; ++e) {
            int idx = e * NTHREADS + tid;
            int k = idx & 15, m = idx >> 4;
            As[k][m] = w4[(m0 + m) * CHALF + k0 + k];
        }
#pragma unroll
        for (int e = 0; e < 8; ++e) {
            int idx = e * NTHREADS + tid;
            int n = idx & 127, k = idx >> 7;
            Bs[k][n] = yb[(size_t)(k0 + k) * NPIX + n0 + n];
        }
        __syncthreads();
#pragma unroll
        for (int k = 0; k < BK; ++k) {
            float a[TM], bb[TN];
            *(float4*)&a[0]  = *(const float4*)&As[k][ty * TM];
            *(float4*)&a[4]  = *(const float4*)&As[k][ty * TM + 4];
            *(float4*)&bb[0] = *(const float4*)&Bs[k][tx * TN];
            *(float4*)&bb[4] = *(const float4*)&Bs[k][tx * TN + 4];
#pragma unroll
            for (int i = 0; i < TM; ++i)
#pragma unroll
                for (int j = 0; j < TN; ++j) acc[i][j] += a[i] * bb[j];
        }
        __syncthreads();
    }

#pragma unroll
    for (int i = 0; i < TM; ++i) {
        int gm = m0 + ty * TM + i;
        float bias = b4[gm];
        size_t off = ((size_t)b * CDIM + gm) * NPIX + n0 + tx * TN;
        float4 x0 = *(const float4*)&x[off];
        float4 x1 = *(const float4*)&x[off + 4];
        float* dst = out + off;
        *(float4*)&dst[0] = make_float4(acc[i][0] + bias + x0.x, acc[i][1] + bias + x0.y,
                                        acc[i][2] + bias + x0.z, acc[i][3] + bias + x0.w);
        *(float4*)&dst[4] = make_float4(acc[i][4] + bias + x1.x, acc[i][5] + bias + x1.y,
                                        acc[i][6] + bias + x1.z, acc[i][7] + bias + x1.w);
    }
}

// ============================================================
extern "C" void kernel_launch(void* const* d_in, const int* in_sizes, int n_in,
                              void* d_out, int out_size)
{
    const float* x  = (const float*)d_in[0];
    const float* w1 = (const float*)d_in[1];
    const float* b1 = (const float*)d_in[2];
    const float* w2 = (const float*)d_in[3];
    const float* b2 = (const float*)d_in[4];
    const float* w3 = (const float*)d_in[5];
    const float* b3 = (const float*)d_in[6];
    const float* w4 = (const float*)d_in[7];
    const float* b4 = (const float*)d_in[8];
    float* out = (float*)d_out;

    const int SC_SMEM = 2 * 128 * SROW;        // 69632
    const int Y_SMEM  = 4 * 128 * YROW;        // 73728
    cudaFuncSetAttribute(scores_mma_kernel, cudaFuncAttributeMaxDynamicSharedMemorySize, SC_SMEM);
    cudaFuncSetAttribute(y_mma_kernel,      cudaFuncAttributeMaxDynamicSharedMemorySize, Y_SMEM);

    proj_kernel      <<<dim3(NPIX / BN, 3, BATCH), NTHREADS>>>(x, w1, b1, w2, b2, w3, b3);
    scores_mma_kernel<<<dim3(NPIX / 128, NPIX / 128, BATCH), 256, SC_SMEM>>>();
    den_part_kernel  <<<dim3(2, 16, BATCH), 256>>>();
    den_reduce_kernel<<<dim3(NPIX / 256, BATCH), 256>>>();
    gscale_kernel    <<<dim3(1024), 256>>>();
    y_mma_kernel     <<<dim3(NPIX / 128, BATCH), 256, Y_SMEM>>>();
    out_kernel       <<<dim3(NPIX / BN, CDIM / BM, BATCH), NTHREADS>>>(x, w4, b4, out);
}

// round 5
// speedup vs baseline: 5.9703x; 1.6472x over previous
#include <cuda_runtime.h>
#include <cuda_bf16.h>
#include <math.h>
#include <stdint.h>

#define BATCH 4
#define CDIM  256
#define CHALF 128
#define NPIX  4096

// ---- scratch (device globals; no dynamic allocation allowed) ----
__device__ __nv_bfloat16 d_wb [3 * CHALF * CDIM];            // w1|w2|w3 bf16 [3][128][256]
__device__ __nv_bfloat16 d_w4b[CDIM * CHALF];                // w4 bf16 [256][128]
__device__ __nv_bfloat16 d_xT [BATCH * NPIX * CDIM];         // x^T [b][n][c] bf16
__device__ __nv_bfloat16 d_thT[BATCH * NPIX * CHALF];        // theta^T [b][i][c] bf16
__device__ __nv_bfloat16 d_phT[BATCH * NPIX * CHALF];        // phi^T   [b][j][c] bf16
__device__ __nv_bfloat16 d_gu [BATCH * CHALF * NPIX];        // g unscaled [b][c][j] bf16
__device__ __nv_bfloat16 d_gs [BATCH * CHALF * NPIX];        // g/den [b][c][j] bf16
__device__ __nv_bfloat16 d_yb [BATCH * NPIX * CHALF];        // y [b][i][c] bf16
__device__ float         d_den [BATCH * NPIX];
__device__ float         d_denp[BATCH * 32 * NPIX];
__device__ __nv_bfloat16 d_E  [(size_t)BATCH * NPIX * NPIX]; // exp(scores) bf16, 128 MB

// ================= helpers =================
__device__ __forceinline__ uint32_t smem_u32(const void* p) {
    uint32_t a;
    asm("{ .reg .u64 t; cvta.to.shared.u64 t, %1; cvt.u32.u64 %0, t; }" : "=r"(a) : "l"(p));
    return a;
}
__device__ __forceinline__ uint32_t pack_bf16x2(float lo, float hi) {
    uint32_t r;
    asm("cvt.rn.bf16x2.f32 %0, %1, %2;" : "=r"(r) : "f"(hi), "f"(lo));
    return r;
}
__device__ __forceinline__ void ldm_x4(uint32_t& r0, uint32_t& r1, uint32_t& r2, uint32_t& r3,
                                       uint32_t addr) {
    asm volatile("ldmatrix.sync.aligned.m8n8.x4.shared.b16 {%0,%1,%2,%3}, [%4];"
                 : "=r"(r0), "=r"(r1), "=r"(r2), "=r"(r3) : "r"(addr));
}
__device__ __forceinline__ void mma_bf16(float* c, const uint32_t* a, const uint32_t* b) {
    asm volatile(
        "mma.sync.aligned.m16n8k16.row.col.f32.bf16.bf16.f32 "
        "{%0,%1,%2,%3}, {%4,%5,%6,%7}, {%8,%9}, {%0,%1,%2,%3};"
        : "+f"(c[0]), "+f"(c[1]), "+f"(c[2]), "+f"(c[3])
        : "r"(a[0]), "r"(a[1]), "r"(a[2]), "r"(a[3]), "r"(b[0]), "r"(b[1]));
}
__device__ __forceinline__ void cp16(uint32_t dst, const void* src) {
    asm volatile("cp.async.cg.shared.global [%0], [%1], 16;" :: "r"(dst), "l"(src) : "memory");
}
__device__ __forceinline__ void cp_commit() { asm volatile("cp.async.commit_group;" ::: "memory"); }
__device__ __forceinline__ void cp_wait0()  { asm volatile("cp.async.wait_group 0;" ::: "memory"); }
__device__ __forceinline__ void cp_wait1()  { asm volatile("cp.async.wait_group 1;" ::: "memory"); }

#define SROW 272   // 128 bf16 row + 16B pad
#define PROW 528   // 256 bf16 row + 16B pad
#define YROW 144   // 64 bf16 row + 16B pad

// ============================================================
// Kernel 0a: weight convert to bf16
// ============================================================
__global__ void wconv_kernel(const float* __restrict__ w1, const float* __restrict__ w2,
                             const float* __restrict__ w3, const float* __restrict__ w4)
{
    int idx = blockIdx.x * 256 + threadIdx.x;   // 131072 total
    if (idx < 98304) {
        int sel = idx >> 15, r = idx & 32767;
        const float* W = (sel == 0) ? w1 : (sel == 1) ? w2 : w3;
        d_wb[idx] = __float2bfloat16(W[r]);
    } else {
        int r = idx - 98304;
        d_w4b[r] = __float2bfloat16(w4[r]);
    }
}

// ============================================================
// Kernel 0b: x transpose-convert: [b][c][n] fp32 -> [b][n][c] bf16
// ============================================================
__global__ void xT_kernel(const float* __restrict__ x)
{
    __shared__ float t[32][33];
    const int n0 = blockIdx.x * 32, c0 = blockIdx.y * 32, b = blockIdx.z;
    const float* xb = x + ((size_t)b * CDIM + c0) * NPIX + n0;
    for (int r = threadIdx.y; r < 32; r += 8)
        t[r][threadIdx.x] = xb[(size_t)r * NPIX + threadIdx.x];
    __syncthreads();
    __nv_bfloat16* o = d_xT + ((size_t)b * NPIX + n0) * CDIM + c0;
    for (int r = threadIdx.y; r < 32; r += 8)
        o[(size_t)r * CDIM + threadIdx.x] = __float2bfloat16(t[threadIdx.x][r]);
}

// ============================================================
// Kernel 1: proj via mma. C[m,n] = W[m,k] xT[n,k], M=128, N=128, K=256.
// sel 0/1 -> thT/phT bf16 [n][m]; sel 2 -> gu bf16 [m][n].
// ============================================================
__global__ __launch_bounds__(256) void proj_mma_kernel(
    const float* __restrict__ b1, const float* __restrict__ b2, const float* __restrict__ b3)
{
    extern __shared__ __align__(16) char smem[];
    char* Asm = smem;               // 128*528 = 67584
    char* Bsm = smem + 67584;
    const uint32_t Asb = smem_u32(Asm), Bsb = smem_u32(Bsm);

    const int tid = threadIdx.x, wid = tid >> 5, lane = tid & 31;
    const int n0 = blockIdx.x * 128, sel = blockIdx.y, b = blockIdx.z;
    const float* Bv = (sel == 0) ? b1 : (sel == 1) ? b2 : b3;

    const __nv_bfloat16* W = d_wb + (size_t)sel * CHALF * CDIM;
    const __nv_bfloat16* X = d_xT + ((size_t)b * NPIX + n0) * CDIM;

#pragma unroll
    for (int e = 0; e < 16; ++e) {
        int idx = e * 256 + tid;
        int row = idx >> 5, kb = idx & 31;
        *(uint4*)(Asm + row * PROW + kb * 16) = *(const uint4*)(W + (size_t)row * CDIM + kb * 8);
        *(uint4*)(Bsm + row * PROW + kb * 16) = *(const uint4*)(X + (size_t)row * CDIM + kb * 8);
    }
    __syncthreads();

    const int wm = (wid & 3) * 32, wn = (wid >> 2) * 64;
    const int id = lane >> 3, l7 = lane & 7;

    float acc[2][8][4];
#pragma unroll
    for (int am = 0; am < 2; ++am)
#pragma unroll
        for (int an = 0; an < 8; ++an)
#pragma unroll
            for (int q = 0; q < 4; ++q) acc[am][an][q] = 0.f;

#pragma unroll
    for (int ks = 0; ks < 16; ++ks) {
        uint32_t a[2][4];
#pragma unroll
        for (int am = 0; am < 2; ++am) {
            uint32_t addr = Asb + (uint32_t)(wm + am * 16 + (id & 1) * 8 + l7) * PROW
                          + (uint32_t)(ks * 16 + (id >> 1) * 8) * 2;
            ldm_x4(a[am][0], a[am][1], a[am][2], a[am][3], addr);
        }
        uint32_t bf[8][2];
#pragma unroll
        for (int p = 0; p < 4; ++p) {
            uint32_t r0, r1, r2, r3;
            uint32_t addr = Bsb + (uint32_t)(wn + p * 16 + (id >> 1) * 8 + l7) * PROW
                          + (uint32_t)(ks * 16 + (id & 1) * 8) * 2;
            ldm_x4(r0, r1, r2, r3, addr);
            bf[p * 2][0] = r0; bf[p * 2][1] = r1;
            bf[p * 2 + 1][0] = r2; bf[p * 2 + 1][1] = r3;
        }
#pragma unroll
        for (int am = 0; am < 2; ++am)
#pragma unroll
            for (int an = 0; an < 8; ++an)
                mma_bf16(acc[am][an], a[am], bf[an]);
    }
    __syncthreads();

    char* Es = smem;
    const int gID = lane >> 2, tig = lane & 3;

    if (sel < 2) {
        // stage transposed [n][m] bf16 (stride 272), bias per m
#pragma unroll
        for (int am = 0; am < 2; ++am) {
            float bias0 = Bv[wm + am * 16 + gID];
            float bias1 = Bv[wm + am * 16 + gID + 8];
            int mm = wm + am * 16 + gID;
#pragma unroll
            for (int an = 0; an < 8; ++an) {
                int nn = wn + an * 8 + 2 * tig;
                *(__nv_bfloat16*)(Es + nn * SROW + mm * 2)           = __float2bfloat16(acc[am][an][0] + bias0);
                *(__nv_bfloat16*)(Es + (nn + 1) * SROW + mm * 2)     = __float2bfloat16(acc[am][an][1] + bias0);
                *(__nv_bfloat16*)(Es + nn * SROW + (mm + 8) * 2)     = __float2bfloat16(acc[am][an][2] + bias1);
                *(__nv_bfloat16*)(Es + (nn + 1) * SROW + (mm + 8) * 2) = __float2bfloat16(acc[am][an][3] + bias1);
            }
        }
        __syncthreads();
        __nv_bfloat16* O = ((sel == 0) ? d_thT : d_phT) + (size_t)b * NPIX * CHALF;
#pragma unroll
        for (int e = 0; e < 8; ++e) {
            int idx = e * 256 + tid;
            int row = idx >> 4, kb = idx & 15;
            *(uint4*)(O + (size_t)(n0 + row) * CHALF + kb * 8) = *(const uint4*)(Es + row * SROW + kb * 16);
        }
    } else {
        // stage [m][n] bf16 (stride 272), bias per m
#pragma unroll
        for (int am = 0; am < 2; ++am) {
            float bias0 = Bv[wm + am * 16 + gID];
            float bias1 = Bv[wm + am * 16 + gID + 8];
            int mm = wm + am * 16 + gID;
#pragma unroll
            for (int an = 0; an < 8; ++an) {
                int nn = wn + an * 8 + 2 * tig;
                *(uint32_t*)(Es + mm * SROW + nn * 2)       = pack_bf16x2(acc[am][an][0] + bias0, acc[am][an][1] + bias0);
                *(uint32_t*)(Es + (mm + 8) * SROW + nn * 2) = pack_bf16x2(acc[am][an][2] + bias1, acc[am][an][3] + bias1);
            }
        }
        __syncthreads();
        __nv_bfloat16* O = d_gu + (size_t)b * CHALF * NPIX;
#pragma unroll
        for (int e = 0; e < 8; ++e) {
            int idx = e * 256 + tid;
            int row = idx >> 4, kb = idx & 15;
            *(uint4*)(O + (size_t)row * NPIX + n0 + kb * 8) = *(const uint4*)(Es + row * SROW + kb * 16);
        }
    }
}

// ============================================================
// Kernel 2: scores via mma. CTA tile 128(i) x 128(j), K=128.
// E -> bf16 gmem; fused per-i-tile column sums -> d_denp.
// ============================================================
__global__ __launch_bounds__(256) void scores_mma_kernel()
{
    extern __shared__ __align__(16) char smem[];
    char* Asm = smem;              // 128 * 272 = 34816
    char* Bsm = smem + 34816;
    const uint32_t Asb = smem_u32(Asm), Bsb = smem_u32(Bsm);

    const int tid = threadIdx.x, wid = tid >> 5, lane = tid & 31;
    const int j0 = blockIdx.x * 128, i0 = blockIdx.y * 128, b = blockIdx.z;

    const __nv_bfloat16* Ath = d_thT + ((size_t)b * NPIX + i0) * CHALF;
    const __nv_bfloat16* Bph = d_phT + ((size_t)b * NPIX + j0) * CHALF;

#pragma unroll
    for (int e = 0; e < 8; ++e) {
        int idx = e * 256 + tid;
        int row = idx >> 4, kb = idx & 15;
        *(uint4*)(Asm + row * SROW + kb * 16) = *(const uint4*)(Ath + (size_t)row * CHALF + kb * 8);
        *(uint4*)(Bsm + row * SROW + kb * 16) = *(const uint4*)(Bph + (size_t)row * CHALF + kb * 8);
    }
    __syncthreads();

    const int wm = (wid & 3) * 32, wn = (wid >> 2) * 64;
    const int id = lane >> 3, l7 = lane & 7;

    float acc[2][8][4];
#pragma unroll
    for (int am = 0; am < 2; ++am)
#pragma unroll
        for (int an = 0; an < 8; ++an)
#pragma unroll
            for (int q = 0; q < 4; ++q) acc[am][an][q] = 0.f;

#pragma unroll
    for (int ks = 0; ks < 8; ++ks) {
        uint32_t a[2][4];
#pragma unroll
        for (int am = 0; am < 2; ++am) {
            uint32_t addr = Asb + (uint32_t)(wm + am * 16 + (id & 1) * 8 + l7) * SROW
                          + (uint32_t)(ks * 16 + (id >> 1) * 8) * 2;
            ldm_x4(a[am][0], a[am][1], a[am][2], a[am][3], addr);
        }
        uint32_t bf[8][2];
#pragma unroll
        for (int p = 0; p < 4; ++p) {
            uint32_t r0, r1, r2, r3;
            uint32_t addr = Bsb + (uint32_t)(wn + p * 16 + (id >> 1) * 8 + l7) * SROW
                          + (uint32_t)(ks * 16 + (id & 1) * 8) * 2;
            ldm_x4(r0, r1, r2, r3, addr);
            bf[p * 2][0] = r0; bf[p * 2][1] = r1;
            bf[p * 2 + 1][0] = r2; bf[p * 2 + 1][1] = r3;
        }
#pragma unroll
        for (int am = 0; am < 2; ++am)
#pragma unroll
            for (int an = 0; an < 8; ++an)
                mma_bf16(acc[am][an], a[am], bf[an]);
    }
    __syncthreads();

    // epilogue: exp -> bf16, stage [m][n] in smem
    char* Es = smem;
    const int gID = lane >> 2, tig = lane & 3;
#pragma unroll
    for (int am = 0; am < 2; ++am)
#pragma unroll
        for (int an = 0; an < 8; ++an) {
            int m0 = wm + am * 16, n0 = wn + an * 8 + 2 * tig;
            float e0 = __expf(acc[am][an][0]), e1 = __expf(acc[am][an][1]);
            float e2 = __expf(acc[am][an][2]), e3 = __expf(acc[am][an][3]);
            *(uint32_t*)(Es + (m0 + gID) * SROW + n0 * 2)     = pack_bf16x2(e0, e1);
            *(uint32_t*)(Es + (m0 + gID + 8) * SROW + n0 * 2) = pack_bf16x2(e2, e3);
        }
    __syncthreads();

    // write E tile (coalesced)
    __nv_bfloat16* Eb = d_E + ((size_t)b * NPIX + i0) * NPIX + j0;
#pragma unroll
    for (int e = 0; e < 8; ++e) {
        int idx = e * 256 + tid;
        int row = idx >> 4, kb = idx & 15;
        *(uint4*)(Eb + (size_t)row * NPIX + kb * 8) = *(const uint4*)(Es + row * SROW + kb * 16);
    }

    // fused deterministic column sums from staged bf16 tile
    float* sums = (float*)(smem + 34816);
    {
        int col = tid & 127, half = tid >> 7;
        const char* base = Es + col * 2 + half * 64 * SROW;
        float s = 0.f;
#pragma unroll 8
        for (int r = 0; r < 64; ++r)
            s += __bfloat162float(*(const __nv_bfloat16*)(base + r * SROW));
        sums[half * 128 + col] = s;
    }
    __syncthreads();
    if (tid < 128)
        d_denp[((size_t)b * 32 + blockIdx.y) * NPIX + j0 + tid] = sums[tid] + sums[128 + tid];
}

// ============================================================
// Kernel 3: den reduce over 32 i-tile partials (deterministic)
// ============================================================
__global__ void den_reduce_kernel()
{
    int j = blockIdx.x * 256 + threadIdx.x;
    int b = blockIdx.y;
    float s = 0.f;
#pragma unroll
    for (int t = 0; t < 32; ++t) s += d_denp[((size_t)b * 32 + t) * NPIX + j];
    d_den[b * NPIX + j] = s;
}

// ============================================================
// Kernel 4: gs[b][c][j] = bf16(gu[b][c][j] / den[j])
// ============================================================
__global__ void gscale_kernel()
{
    int idx = blockIdx.x * 256 + threadIdx.x;
    int j  = (idx & (NPIX / 8 - 1)) * 8;
    int c  = (idx >> 9) & (CHALF - 1);
    int b  = idx >> 16;
    size_t off = ((size_t)b * CHALF + c) * NPIX + j;
    uint4 gv = *(const uint4*)(d_gu + off);
    const float* dp = d_den + b * NPIX + j;
    float4 e0 = *(const float4*)&dp[0], e1 = *(const float4*)&dp[4];
    const uint32_t* h = (const uint32_t*)&gv;
    float gf[8];
#pragma unroll
    for (int q = 0; q < 4; ++q) {
        gf[2 * q]     = __uint_as_float(h[q] << 16);
        gf[2 * q + 1] = __uint_as_float(h[q] & 0xffff0000u);
    }
    uint4 o;
    o.x = pack_bf16x2(gf[0] / e0.x, gf[1] / e0.y);
    o.y = pack_bf16x2(gf[2] / e0.z, gf[3] / e0.w);
    o.z = pack_bf16x2(gf[4] / e1.x, gf[5] / e1.y);
    o.w = pack_bf16x2(gf[6] / e1.z, gf[7] / e1.w);
    *(uint4*)(d_gs + off) = o;
}

// ============================================================
// Kernel 5: y via mma. CTA tile 128(i) x 128(c), K=4096, cp.async x2 buffers.
// y stored bf16 [b][i][c] (natural [m][n] layout).
// ============================================================
__global__ __launch_bounds__(256) void y_mma_kernel()
{
    extern __shared__ __align__(16) char smem[];
    const uint32_t sb = smem_u32(smem);

    const int tid = threadIdx.x, wid = tid >> 5, lane = tid & 31;
    const int i0 = blockIdx.x * 128, b = blockIdx.y;

    const __nv_bfloat16* Ebase = d_E  + ((size_t)b * NPIX + i0) * NPIX;
    const __nv_bfloat16* Gbase = d_gs + (size_t)b * CHALF * NPIX;

    const int wm = (wid & 3) * 32, wn = (wid >> 2) * 64;
    const int id = lane >> 3, l7 = lane & 7;

    float acc[2][8][4];
#pragma unroll
    for (int am = 0; am < 2; ++am)
#pragma unroll
        for (int an = 0; an < 8; ++an)
#pragma unroll
            for (int q = 0; q < 4; ++q) acc[am][an][q] = 0.f;

    const int lrow = tid >> 1;
    const int lcol = (tid & 1) * 4;

    auto issue_chunk = [&](int c, int bufsel) {
        uint32_t Ab = sb + (uint32_t)bufsel * 36864;
        uint32_t Bb = Ab + 18432;
        size_t k0 = (size_t)c * 64;
#pragma unroll
        for (int q = 0; q < 4; ++q) {
            cp16(Ab + lrow * YROW + (lcol + q) * 16, Ebase + (size_t)lrow * NPIX + k0 + (lcol + q) * 8);
            cp16(Bb + lrow * YROW + (lcol + q) * 16, Gbase + (size_t)lrow * NPIX + k0 + (lcol + q) * 8);
        }
    };

    issue_chunk(0, 0);
    cp_commit();

    for (int c = 0; c < 64; ++c) {
        if (c + 1 < 64) {
            issue_chunk(c + 1, (c + 1) & 1);
            cp_commit();
            cp_wait1();
        } else {
            cp_wait0();
        }
        __syncthreads();

        uint32_t Ab = sb + (uint32_t)(c & 1) * 36864;
        uint32_t Bb = Ab + 18432;
#pragma unroll
        for (int ks = 0; ks < 4; ++ks) {
            uint32_t a[2][4];
#pragma unroll
            for (int am = 0; am < 2; ++am) {
                uint32_t addr = Ab + (uint32_t)(wm + am * 16 + (id & 1) * 8 + l7) * YROW
                              + (uint32_t)(ks * 16 + (id >> 1) * 8) * 2;
                ldm_x4(a[am][0], a[am][1], a[am][2], a[am][3], addr);
            }
            uint32_t bf[8][2];
#pragma unroll
            for (int p = 0; p < 4; ++p) {
                uint32_t r0, r1, r2, r3;
                uint32_t addr = Bb + (uint32_t)(wn + p * 16 + (id >> 1) * 8 + l7) * YROW
                              + (uint32_t)(ks * 16 + (id & 1) * 8) * 2;
                ldm_x4(r0, r1, r2, r3, addr);
                bf[p * 2][0] = r0; bf[p * 2][1] = r1;
                bf[p * 2 + 1][0] = r2; bf[p * 2 + 1][1] = r3;
            }
#pragma unroll
            for (int am = 0; am < 2; ++am)
#pragma unroll
                for (int an = 0; an < 8; ++an)
                    mma_bf16(acc[am][an], a[am], bf[an]);
        }
        __syncthreads();
    }

    // epilogue: stage bf16 [m=i][n=c] (stride 272), coalesced store to d_yb
    char* Es = smem;
    const int gID = lane >> 2, tig = lane & 3;
#pragma unroll
    for (int am = 0; am < 2; ++am)
#pragma unroll
        for (int an = 0; an < 8; ++an) {
            int mm = wm + am * 16 + gID, nn = wn + an * 8 + 2 * tig;
            *(uint32_t*)(Es + mm * SROW + nn * 2)       = pack_bf16x2(acc[am][an][0], acc[am][an][1]);
            *(uint32_t*)(Es + (mm + 8) * SROW + nn * 2) = pack_bf16x2(acc[am][an][2], acc[am][an][3]);
        }
    __syncthreads();

    __nv_bfloat16* yb = d_yb + ((size_t)b * NPIX + i0) * CHALF;
#pragma unroll
    for (int e = 0; e < 8; ++e) {
        int idx = e * 256 + tid;
        int row = idx >> 4, kb = idx & 15;
        *(uint4*)(yb + (size_t)row * CHALF + kb * 8) = *(const uint4*)(Es + row * SROW + kb * 16);
    }
}

// ============================================================
// Kernel 6: out via mma. C[m=o][n=i] = w4[o,c] yb[i,c]; + bias + x residual.
// M=128 (o-tile), N=128 (i-tile), K=128.
// ============================================================
__global__ __launch_bounds__(256) void out_mma_kernel(
    const float* __restrict__ x, const float* __restrict__ b4, float* __restrict__ out)
{
    extern __shared__ __align__(16) char smem[];
    char* Asm = smem;              // 128 * 272
    char* Bsm = smem + 34816;
    const uint32_t Asb = smem_u32(Asm), Bsb = smem_u32(Bsm);

    const int tid = threadIdx.x, wid = tid >> 5, lane = tid & 31;
    const int i0 = blockIdx.x * 128, o0 = blockIdx.y * 128, b = blockIdx.z;

    const __nv_bfloat16* A = d_w4b + (size_t)o0 * CHALF;
    const __nv_bfloat16* Bt = d_yb + ((size_t)b * NPIX + i0) * CHALF;

#pragma unroll
    for (int e = 0; e < 8; ++e) {
        int idx = e * 256 + tid;
        int row = idx >> 4, kb = idx & 15;
        *(uint4*)(Asm + row * SROW + kb * 16) = *(const uint4*)(A + (size_t)row * CHALF + kb * 8);
        *(uint4*)(Bsm + row * SROW + kb * 16) = *(const uint4*)(Bt + (size_t)row * CHALF + kb * 8);
    }
    __syncthreads();

    const int wm = (wid & 3) * 32, wn = (wid >> 2) * 64;
    const int id = lane >> 3, l7 = lane & 7;

    float acc[2][8][4];
#pragma unroll
    for (int am = 0; am < 2; ++am)
#pragma unroll
        for (int an = 0; an < 8; ++an)
#pragma unroll
            for (int q = 0; q < 4; ++q) acc[am][an][q] = 0.f;

#pragma unroll
    for (int ks = 0; ks < 8; ++ks) {
        uint32_t a[2][4];
#pragma unroll
        for (int am = 0; am < 2; ++am) {
            uint32_t addr = Asb + (uint32_t)(wm + am * 16 + (id & 1) * 8 + l7) * SROW
                          + (uint32_t)(ks * 16 + (id >> 1) * 8) * 2;
            ldm_x4(a[am][0], a[am][1], a[am][2], a[am][3], addr);
        }
        uint32_t bf[8][2];
#pragma unroll
        for (int p = 0; p < 4; ++p) {
            uint32_t r0, r1, r2, r3;
            uint32_t addr = Bsb + (uint32_t)(wn + p * 16 + (id >> 1) * 8 + l7) * SROW
                          + (uint32_t)(ks * 16 + (id & 1) * 8) * 2;
            ldm_x4(r0, r1, r2, r3, addr);
            bf[p * 2][0] = r0; bf[p * 2][1] = r1;
            bf[p * 2 + 1][0] = r2; bf[p * 2 + 1][1] = r3;
        }
#pragma unroll
        for (int am = 0; am < 2; ++am)
#pragma unroll
            for (int an = 0; an < 8; ++an)
                mma_bf16(acc[am][an], a[am], bf[an]);
    }
    __syncthreads();

    // stage fp32 [m][n] (stride 132 floats), then add bias + x and write
    float* Ys = (float*)smem;
    const int gID = lane >> 2, tig = lane & 3;
#pragma unroll
    for (int am = 0; am < 2; ++am)
#pragma unroll
        for (int an = 0; an < 8; ++an) {
            int mm = wm + am * 16 + gID, nn = wn + an * 8 + 2 * tig;
            *(float2*)(Ys + mm * 132 + nn)       = make_float2(acc[am][an][0], acc[am][an][1]);
            *(float2*)(Ys + (mm + 8) * 132 + nn) = make_float2(acc[am][an][2], acc[am][an][3]);
        }
    __syncthreads();

#pragma unroll
    for (int e = 0; e < 16; ++e) {
        int idx = e * 256 + tid;
        int row = idx >> 5, col = (idx & 31) * 4;
        float bias = b4[o0 + row];
        size_t off = ((size_t)b * CDIM + o0 + row) * NPIX + i0 + col;
        float4 v = *(const float4*)(Ys + row * 132 + col);
        float4 xv = *(const float4*)&x[off];
        *(float4*)&out[off] = make_float4(v.x + bias + xv.x, v.y + bias + xv.y,
                                          v.z + bias + xv.z, v.w + bias + xv.w);
    }
}

// ============================================================
extern "C" void kernel_launch(void* const* d_in, const int* in_sizes, int n_in,
                              void* d_out, int out_size)
{
    const float* x  = (const float*)d_in[0];
    const float* w1 = (const float*)d_in[1];
    const float* b1 = (const float*)d_in[2];
    const float* w2 = (const float*)d_in[3];
    const float* b2 = (const float*)d_in[4];
    const float* w3 = (const float*)d_in[5];
    const float* b3 = (const float*)d_in[6];
    const float* w4 = (const float*)d_in[7];
    const float* b4 = (const float*)d_in[8];
    float* out = (float*)d_out;

    const int P_SMEM  = 2 * 128 * PROW;        // 135168
    const int SC_SMEM = 2 * 128 * SROW;        // 69632
    const int Y_SMEM  = 4 * 128 * YROW;        // 73728
    const int O_SMEM  = 2 * 128 * SROW;        // 69632
    cudaFuncSetAttribute(proj_mma_kernel,   cudaFuncAttributeMaxDynamicSharedMemorySize, P_SMEM);
    cudaFuncSetAttribute(scores_mma_kernel, cudaFuncAttributeMaxDynamicSharedMemorySize, SC_SMEM);
    cudaFuncSetAttribute(y_mma_kernel,      cudaFuncAttributeMaxDynamicSharedMemorySize, Y_SMEM);
    cudaFuncSetAttribute(out_mma_kernel,    cudaFuncAttributeMaxDynamicSharedMemorySize, O_SMEM);

    wconv_kernel     <<<512, 256>>>(w1, w2, w3, w4);
    xT_kernel        <<<dim3(NPIX / 32, CDIM / 32, BATCH), dim3(32, 8)>>>(x);
    proj_mma_kernel  <<<dim3(NPIX / 128, 3, BATCH), 256, P_SMEM>>>(b1, b2, b3);
    scores_mma_kernel<<<dim3(NPIX / 128, NPIX / 128, BATCH), 256, SC_SMEM>>>();
    den_reduce_kernel<<<dim3(NPIX / 256, BATCH), 256>>>();
    gscale_kernel    <<<dim3(1024), 256>>>();
    y_mma_kernel     <<<dim3(NPIX / 128, BATCH), 256, Y_SMEM>>>();
    out_mma_kernel   <<<dim3(NPIX / 128, CDIM / 128, BATCH), 256, O_SMEM>>>(x, b4, out);
}

// round 6
// speedup vs baseline: 7.4186x; 1.2426x over previous
#include <cuda_runtime.h>
#include <cuda_bf16.h>
#include <math.h>
#include <stdint.h>

#define BATCH 4
#define CDIM  256
#define CHALF 128
#define NPIX  4096

// ---- scratch (device globals; no dynamic allocation allowed) ----
__device__ __nv_bfloat16 d_wb [3 * CHALF * CDIM];            // w1|w2|w3 bf16 [3][128][256]
__device__ __nv_bfloat16 d_w4b[CDIM * CHALF];                // w4 bf16 [256][128]
__device__ __nv_bfloat16 d_xT [BATCH * NPIX * CDIM];         // x^T [b][n][c] bf16
__device__ __nv_bfloat16 d_thT[BATCH * NPIX * CHALF];        // theta^T [b][i][c] bf16
__device__ __nv_bfloat16 d_phT[BATCH * NPIX * CHALF];        // phi^T   [b][j][c] bf16
__device__ __nv_bfloat16 d_gu [BATCH * CHALF * NPIX];        // g unscaled [b][c][j] bf16
__device__ __nv_bfloat16 d_gs [BATCH * CHALF * NPIX];        // g/den [b][c][j] bf16
__device__ __nv_bfloat16 d_yb [BATCH * NPIX * CHALF];        // y [b][i][c] bf16
__device__ float         d_den [BATCH * NPIX];
__device__ float         d_denp[BATCH * 32 * NPIX];
__device__ __nv_bfloat16 d_E  [(size_t)BATCH * NPIX * NPIX]; // exp(scores) bf16, 128 MB

// ================= helpers =================
__device__ __forceinline__ uint32_t smem_u32(const void* p) {
    uint32_t a;
    asm("{ .reg .u64 t; cvta.to.shared.u64 t, %1; cvt.u32.u64 %0, t; }" : "=r"(a) : "l"(p));
    return a;
}
__device__ __forceinline__ uint32_t pack_bf16x2(float lo, float hi) {
    uint32_t r;
    asm("cvt.rn.bf16x2.f32 %0, %1, %2;" : "=r"(r) : "f"(hi), "f"(lo));
    return r;
}
__device__ __forceinline__ void ldm_x4(uint32_t& r0, uint32_t& r1, uint32_t& r2, uint32_t& r3,
                                       uint32_t addr) {
    asm volatile("ldmatrix.sync.aligned.m8n8.x4.shared.b16 {%0,%1,%2,%3}, [%4];"
                 : "=r"(r0), "=r"(r1), "=r"(r2), "=r"(r3) : "r"(addr));
}
__device__ __forceinline__ void mma_bf16(float* c, const uint32_t* a, const uint32_t* b) {
    asm volatile(
        "mma.sync.aligned.m16n8k16.row.col.f32.bf16.bf16.f32 "
        "{%0,%1,%2,%3}, {%4,%5,%6,%7}, {%8,%9}, {%0,%1,%2,%3};"
        : "+f"(c[0]), "+f"(c[1]), "+f"(c[2]), "+f"(c[3])
        : "r"(a[0]), "r"(a[1]), "r"(a[2]), "r"(a[3]), "r"(b[0]), "r"(b[1]));
}
__device__ __forceinline__ void cp16(uint32_t dst, const void* src) {
    asm volatile("cp.async.cg.shared.global [%0], [%1], 16;" :: "r"(dst), "l"(src) : "memory");
}
__device__ __forceinline__ void cp_commit() { asm volatile("cp.async.commit_group;" ::: "memory"); }
__device__ __forceinline__ void cp_wait0()  { asm volatile("cp.async.wait_group 0;" ::: "memory"); }
__device__ __forceinline__ void cp_wait1()  { asm volatile("cp.async.wait_group 1;" ::: "memory"); }

#define SROW 272   // 128 bf16 row + 16B pad
#define PROW 528   // 256 bf16 row + 16B pad

// ============================================================
// Kernel 0a: weight convert to bf16
// ============================================================
__global__ void wconv_kernel(const float* __restrict__ w1, const float* __restrict__ w2,
                             const float* __restrict__ w3, const float* __restrict__ w4)
{
    int idx = blockIdx.x * 256 + threadIdx.x;   // 131072 total
    if (idx < 98304) {
        int sel = idx >> 15, r = idx & 32767;
        const float* W = (sel == 0) ? w1 : (sel == 1) ? w2 : w3;
        d_wb[idx] = __float2bfloat16(W[r]);
    } else {
        int r = idx - 98304;
        d_w4b[r] = __float2bfloat16(w4[r]);
    }
}

// ============================================================
// Kernel 0b: x transpose-convert: [b][c][n] fp32 -> [b][n][c] bf16
// ============================================================
__global__ void xT_kernel(const float* __restrict__ x)
{
    __shared__ float t[32][33];
    const int n0 = blockIdx.x * 32, c0 = blockIdx.y * 32, b = blockIdx.z;
    const float* xb = x + ((size_t)b * CDIM + c0) * NPIX + n0;
    for (int r = threadIdx.y; r < 32; r += 8)
        t[r][threadIdx.x] = xb[(size_t)r * NPIX + threadIdx.x];
    __syncthreads();
    __nv_bfloat16* o = d_xT + ((size_t)b * NPIX + n0) * CDIM + c0;
    for (int r = threadIdx.y; r < 32; r += 8)
        o[(size_t)r * CDIM + threadIdx.x] = __float2bfloat16(t[threadIdx.x][r]);
}

// ============================================================
// Kernel 1: proj via mma. C[m,n] = W[m,k] xT[n,k], M=128, N=128, K=256.
// sel 0/1 -> thT/phT bf16 [n][m]; sel 2 -> gu bf16 [m][n].
// ============================================================
__global__ __launch_bounds__(256) void proj_mma_kernel(
    const float* __restrict__ b1, const float* __restrict__ b2, const float* __restrict__ b3)
{
    extern __shared__ __align__(16) char smem[];
    char* Asm = smem;               // 128*528 = 67584
    char* Bsm = smem + 67584;
    const uint32_t Asb = smem_u32(Asm), Bsb = smem_u32(Bsm);

    const int tid = threadIdx.x, wid = tid >> 5, lane = tid & 31;
    const int n0 = blockIdx.x * 128, sel = blockIdx.y, b = blockIdx.z;
    const float* Bv = (sel == 0) ? b1 : (sel == 1) ? b2 : b3;

    const __nv_bfloat16* W = d_wb + (size_t)sel * CHALF * CDIM;
    const __nv_bfloat16* X = d_xT + ((size_t)b * NPIX + n0) * CDIM;

#pragma unroll
    for (int e = 0; e < 16; ++e) {
        int idx = e * 256 + tid;
        int row = idx >> 5, kb = idx & 31;
        *(uint4*)(Asm + row * PROW + kb * 16) = *(const uint4*)(W + (size_t)row * CDIM + kb * 8);
        *(uint4*)(Bsm + row * PROW + kb * 16) = *(const uint4*)(X + (size_t)row * CDIM + kb * 8);
    }
    __syncthreads();

    const int wm = (wid & 3) * 32, wn = (wid >> 2) * 64;
    const int id = lane >> 3, l7 = lane & 7;

    float acc[2][8][4];
#pragma unroll
    for (int am = 0; am < 2; ++am)
#pragma unroll
        for (int an = 0; an < 8; ++an)
#pragma unroll
            for (int q = 0; q < 4; ++q) acc[am][an][q] = 0.f;

#pragma unroll
    for (int ks = 0; ks < 16; ++ks) {
        uint32_t a[2][4];
#pragma unroll
        for (int am = 0; am < 2; ++am) {
            uint32_t addr = Asb + (uint32_t)(wm + am * 16 + (id & 1) * 8 + l7) * PROW
                          + (uint32_t)(ks * 16 + (id >> 1) * 8) * 2;
            ldm_x4(a[am][0], a[am][1], a[am][2], a[am][3], addr);
        }
        uint32_t bf[8][2];
#pragma unroll
        for (int p = 0; p < 4; ++p) {
            uint32_t r0, r1, r2, r3;
            uint32_t addr = Bsb + (uint32_t)(wn + p * 16 + (id >> 1) * 8 + l7) * PROW
                          + (uint32_t)(ks * 16 + (id & 1) * 8) * 2;
            ldm_x4(r0, r1, r2, r3, addr);
            bf[p * 2][0] = r0; bf[p * 2][1] = r1;
            bf[p * 2 + 1][0] = r2; bf[p * 2 + 1][1] = r3;
        }
#pragma unroll
        for (int am = 0; am < 2; ++am)
#pragma unroll
            for (int an = 0; an < 8; ++an)
                mma_bf16(acc[am][an], a[am], bf[an]);
    }
    __syncthreads();

    char* Es = smem;
    const int gID = lane >> 2, tig = lane & 3;

    if (sel < 2) {
        // stage transposed [n][m] bf16 (stride 272), bias per m
#pragma unroll
        for (int am = 0; am < 2; ++am) {
            float bias0 = Bv[wm + am * 16 + gID];
            float bias1 = Bv[wm + am * 16 + gID + 8];
            int mm = wm + am * 16 + gID;
#pragma unroll
            for (int an = 0; an < 8; ++an) {
                int nn = wn + an * 8 + 2 * tig;
                *(__nv_bfloat16*)(Es + nn * SROW + mm * 2)           = __float2bfloat16(acc[am][an][0] + bias0);
                *(__nv_bfloat16*)(Es + (nn + 1) * SROW + mm * 2)     = __float2bfloat16(acc[am][an][1] + bias0);
                *(__nv_bfloat16*)(Es + nn * SROW + (mm + 8) * 2)     = __float2bfloat16(acc[am][an][2] + bias1);
                *(__nv_bfloat16*)(Es + (nn + 1) * SROW + (mm + 8) * 2) = __float2bfloat16(acc[am][an][3] + bias1);
            }
        }
        __syncthreads();
        __nv_bfloat16* O = ((sel == 0) ? d_thT : d_phT) + (size_t)b * NPIX * CHALF;
#pragma unroll
        for (int e = 0; e < 8; ++e) {
            int idx = e * 256 + tid;
            int row = idx >> 4, kb = idx & 15;
            *(uint4*)(O + (size_t)(n0 + row) * CHALF + kb * 8) = *(const uint4*)(Es + row * SROW + kb * 16);
        }
    } else {
        // stage [m][n] bf16 (stride 272), bias per m
#pragma unroll
        for (int am = 0; am < 2; ++am) {
            float bias0 = Bv[wm + am * 16 + gID];
            float bias1 = Bv[wm + am * 16 + gID + 8];
            int mm = wm + am * 16 + gID;
#pragma unroll
            for (int an = 0; an < 8; ++an) {
                int nn = wn + an * 8 + 2 * tig;
                *(uint32_t*)(Es + mm * SROW + nn * 2)       = pack_bf16x2(acc[am][an][0] + bias0, acc[am][an][1] + bias0);
                *(uint32_t*)(Es + (mm + 8) * SROW + nn * 2) = pack_bf16x2(acc[am][an][2] + bias1, acc[am][an][3] + bias1);
            }
        }
        __syncthreads();
        __nv_bfloat16* O = d_gu + (size_t)b * CHALF * NPIX;
#pragma unroll
        for (int e = 0; e < 8; ++e) {
            int idx = e * 256 + tid;
            int row = idx >> 4, kb = idx & 15;
            *(uint4*)(O + (size_t)row * NPIX + n0 + kb * 8) = *(const uint4*)(Es + row * SROW + kb * 16);
        }
    }
}

// ============================================================
// Kernel 2: scores via mma. CTA tile 128(i) x 128(j), K=128.
// E -> bf16 gmem; column sums via register shuffles (no smem re-read).
// ============================================================
__global__ __launch_bounds__(256) void scores_mma_kernel()
{
    extern __shared__ __align__(16) char smem[];
    char* Asm = smem;              // 128 * 272 = 34816
    char* Bsm = smem + 34816;
    float* sums = (float*)(smem + 69632);   // [4][128] fp32 = 2KB
    const uint32_t Asb = smem_u32(Asm), Bsb = smem_u32(Bsm);

    const int tid = threadIdx.x, wid = tid >> 5, lane = tid & 31;
    const int j0 = blockIdx.x * 128, i0 = blockIdx.y * 128, b = blockIdx.z;

    const __nv_bfloat16* Ath = d_thT + ((size_t)b * NPIX + i0) * CHALF;
    const __nv_bfloat16* Bph = d_phT + ((size_t)b * NPIX + j0) * CHALF;

#pragma unroll
    for (int e = 0; e < 8; ++e) {
        int idx = e * 256 + tid;
        int row = idx >> 4, kb = idx & 15;
        *(uint4*)(Asm + row * SROW + kb * 16) = *(const uint4*)(Ath + (size_t)row * CHALF + kb * 8);
        *(uint4*)(Bsm + row * SROW + kb * 16) = *(const uint4*)(Bph + (size_t)row * CHALF + kb * 8);
    }
    __syncthreads();

    const int wm = (wid & 3) * 32, wn = (wid >> 2) * 64;
    const int id = lane >> 3, l7 = lane & 7;

    float acc[2][8][4];
#pragma unroll
    for (int am = 0; am < 2; ++am)
#pragma unroll
        for (int an = 0; an < 8; ++an)
#pragma unroll
            for (int q = 0; q < 4; ++q) acc[am][an][q] = 0.f;

#pragma unroll
    for (int ks = 0; ks < 8; ++ks) {
        uint32_t a[2][4];
#pragma unroll
        for (int am = 0; am < 2; ++am) {
            uint32_t addr = Asb + (uint32_t)(wm + am * 16 + (id & 1) * 8 + l7) * SROW
                          + (uint32_t)(ks * 16 + (id >> 1) * 8) * 2;
            ldm_x4(a[am][0], a[am][1], a[am][2], a[am][3], addr);
        }
        uint32_t bf[8][2];
#pragma unroll
        for (int p = 0; p < 4; ++p) {
            uint32_t r0, r1, r2, r3;
            uint32_t addr = Bsb + (uint32_t)(wn + p * 16 + (id >> 1) * 8 + l7) * SROW
                          + (uint32_t)(ks * 16 + (id & 1) * 8) * 2;
            ldm_x4(r0, r1, r2, r3, addr);
            bf[p * 2][0] = r0; bf[p * 2][1] = r1;
            bf[p * 2 + 1][0] = r2; bf[p * 2 + 1][1] = r3;
        }
#pragma unroll
        for (int am = 0; am < 2; ++am)
#pragma unroll
            for (int an = 0; an < 8; ++an)
                mma_bf16(acc[am][an], a[am], bf[an]);
    }
    __syncthreads();   // Asm/Bsm reads done; safe to reuse as staging

    // exp in place (fp32)
#pragma unroll
    for (int am = 0; am < 2; ++am)
#pragma unroll
        for (int an = 0; an < 8; ++an)
#pragma unroll
            for (int q = 0; q < 4; ++q) acc[am][an][q] = __expf(acc[am][an][q]);

    // stage E bf16 [m][n] (stride 272)
    char* Es = smem;
    const int gID = lane >> 2, tig = lane & 3;
#pragma unroll
    for (int am = 0; am < 2; ++am)
#pragma unroll
        for (int an = 0; an < 8; ++an) {
            int m0 = wm + am * 16, n0 = wn + an * 8 + 2 * tig;
            *(uint32_t*)(Es + (m0 + gID) * SROW + n0 * 2)     = pack_bf16x2(acc[am][an][0], acc[am][an][1]);
            *(uint32_t*)(Es + (m0 + gID + 8) * SROW + n0 * 2) = pack_bf16x2(acc[am][an][2], acc[am][an][3]);
        }

    // column sums straight from registers: reduce 32 warp rows via shfl
#pragma unroll
    for (int an = 0; an < 8; ++an) {
        float s0 = acc[0][an][0] + acc[0][an][2] + acc[1][an][0] + acc[1][an][2];
        float s1 = acc[0][an][1] + acc[0][an][3] + acc[1][an][1] + acc[1][an][3];
        s0 += __shfl_xor_sync(0xffffffffu, s0, 4);
        s0 += __shfl_xor_sync(0xffffffffu, s0, 8);
        s0 += __shfl_xor_sync(0xffffffffu, s0, 16);
        s1 += __shfl_xor_sync(0xffffffffu, s1, 4);
        s1 += __shfl_xor_sync(0xffffffffu, s1, 8);
        s1 += __shfl_xor_sync(0xffffffffu, s1, 16);
        if (lane < 4) {
            int col = wn + an * 8 + 2 * lane;
            sums[(wid & 3) * 128 + col]     = s0;
            sums[(wid & 3) * 128 + col + 1] = s1;
        }
    }
    __syncthreads();

    // write E tile (coalesced) + den partials
    __nv_bfloat16* Eb = d_E + ((size_t)b * NPIX + i0) * NPIX + j0;
#pragma unroll
    for (int e = 0; e < 8; ++e) {
        int idx = e * 256 + tid;
        int row = idx >> 4, kb = idx & 15;
        *(uint4*)(Eb + (size_t)row * NPIX + kb * 8) = *(const uint4*)(Es + row * SROW + kb * 16);
    }
    if (tid < 128)
        d_denp[((size_t)b * 32 + blockIdx.y) * NPIX + j0 + tid]
            = sums[tid] + sums[128 + tid] + sums[256 + tid] + sums[384 + tid];
}

// ============================================================
// Kernel 3: den reduce over 32 i-tile partials (deterministic, float4)
// ============================================================
__global__ void den_reduce_kernel()
{
    int j = blockIdx.x * 1024 + threadIdx.x * 4;
    int b = blockIdx.y;
    float4 s = make_float4(0.f, 0.f, 0.f, 0.f);
#pragma unroll
    for (int t = 0; t < 32; ++t) {
        float4 v = *(const float4*)&d_denp[((size_t)b * 32 + t) * NPIX + j];
        s.x += v.x; s.y += v.y; s.z += v.z; s.w += v.w;
    }
    *(float4*)&d_den[b * NPIX + j] = s;
}

// ============================================================
// Kernel 4: gs[b][c][j] = bf16(gu[b][c][j] / den[j])
// ============================================================
__global__ void gscale_kernel()
{
    int idx = blockIdx.x * 256 + threadIdx.x;
    int j  = (idx & (NPIX / 8 - 1)) * 8;
    int c  = (idx >> 9) & (CHALF - 1);
    int b  = idx >> 16;
    size_t off = ((size_t)b * CHALF + c) * NPIX + j;
    uint4 gv = *(const uint4*)(d_gu + off);
    const float* dp = d_den + b * NPIX + j;
    float4 e0 = *(const float4*)&dp[0], e1 = *(const float4*)&dp[4];
    const uint32_t* h = (const uint32_t*)&gv;
    float gf[8];
#pragma unroll
    for (int q = 0; q < 4; ++q) {
        gf[2 * q]     = __uint_as_float(h[q] << 16);
        gf[2 * q + 1] = __uint_as_float(h[q] & 0xffff0000u);
    }
    uint4 o;
    o.x = pack_bf16x2(gf[0] / e0.x, gf[1] / e0.y);
    o.y = pack_bf16x2(gf[2] / e0.z, gf[3] / e0.w);
    o.z = pack_bf16x2(gf[4] / e1.x, gf[5] / e1.y);
    o.w = pack_bf16x2(gf[6] / e1.z, gf[7] / e1.w);
    *(uint4*)(d_gs + off) = o;
}

// ============================================================
// Kernel 5: y via mma. CTA tile 128(i) x 128(c), K=4096 in 32 chunks of 128,
// 3-stage cp.async pipeline, ONE barrier per chunk. y stored bf16 [b][i][c].
// stage = A(128x272=34816) + B(34816) = 69632; 3 stages = 208896 B smem.
// ============================================================
__global__ __launch_bounds__(256) void y_mma_kernel()
{
    extern __shared__ __align__(16) char smem[];
    const uint32_t sb = smem_u32(smem);

    const int tid = threadIdx.x, wid = tid >> 5, lane = tid & 31;
    const int i0 = blockIdx.x * 128, b = blockIdx.y;

    const __nv_bfloat16* Ebase = d_E  + ((size_t)b * NPIX + i0) * NPIX;
    const __nv_bfloat16* Gbase = d_gs + (size_t)b * CHALF * NPIX;

    const int wm = (wid & 3) * 32, wn = (wid >> 2) * 64;
    const int id = lane >> 3, l7 = lane & 7;

    float acc[2][8][4];
#pragma unroll
    for (int am = 0; am < 2; ++am)
#pragma unroll
        for (int an = 0; an < 8; ++an)
#pragma unroll
            for (int q = 0; q < 4; ++q) acc[am][an][q] = 0.f;

    auto issue_chunk = [&](int c) {
        uint32_t st = sb + (uint32_t)(c % 3) * 69632;
        size_t k0 = (size_t)c * 128;
#pragma unroll
        for (int e = 0; e < 8; ++e) {
            int idx = e * 256 + tid;
            int row = idx >> 4, kb = idx & 15;
            cp16(st + row * SROW + kb * 16,         Ebase + (size_t)row * NPIX + k0 + kb * 8);
            cp16(st + 34816 + row * SROW + kb * 16, Gbase + (size_t)row * NPIX + k0 + kb * 8);
        }
    };

    issue_chunk(0); cp_commit();
    issue_chunk(1); cp_commit();

    for (int c = 0; c < 32; ++c) {
        if (c < 31) cp_wait1(); else cp_wait0();
        __syncthreads();
        if (c + 2 < 32) { issue_chunk(c + 2); cp_commit(); }

        uint32_t Ab = sb + (uint32_t)(c % 3) * 69632;
        uint32_t Bb = Ab + 34816;
#pragma unroll
        for (int ks = 0; ks < 8; ++ks) {
            uint32_t a[2][4];
#pragma unroll
            for (int am = 0; am < 2; ++am) {
                uint32_t addr = Ab + (uint32_t)(wm + am * 16 + (id & 1) * 8 + l7) * SROW
                              + (uint32_t)(ks * 16 + (id >> 1) * 8) * 2;
                ldm_x4(a[am][0], a[am][1], a[am][2], a[am][3], addr);
            }
            uint32_t bf[8][2];
#pragma unroll
            for (int p = 0; p < 4; ++p) {
                uint32_t r0, r1, r2, r3;
                uint32_t addr = Bb + (uint32_t)(wn + p * 16 + (id >> 1) * 8 + l7) * SROW
                              + (uint32_t)(ks * 16 + (id & 1) * 8) * 2;
                ldm_x4(r0, r1, r2, r3, addr);
                bf[p * 2][0] = r0; bf[p * 2][1] = r1;
                bf[p * 2 + 1][0] = r2; bf[p * 2 + 1][1] = r3;
            }
#pragma unroll
            for (int am = 0; am < 2; ++am)
#pragma unroll
                for (int an = 0; an < 8; ++an)
                    mma_bf16(acc[am][an], a[am], bf[an]);
        }
    }
    __syncthreads();   // all warps done with all stages; reuse stage 0

    // epilogue: stage bf16 [m=i][n=c] (stride 272), coalesced store to d_yb
    char* Es = smem;
    const int gID = lane >> 2, tig = lane & 3;
#pragma unroll
    for (int am = 0; am < 2; ++am)
#pragma unroll
        for (int an = 0; an < 8; ++an) {
            int mm = wm + am * 16 + gID, nn = wn + an * 8 + 2 * tig;
            *(uint32_t*)(Es + mm * SROW + nn * 2)       = pack_bf16x2(acc[am][an][0], acc[am][an][1]);
            *(uint32_t*)(Es + (mm + 8) * SROW + nn * 2) = pack_bf16x2(acc[am][an][2], acc[am][an][3]);
        }
    __syncthreads();

    __nv_bfloat16* yb = d_yb + ((size_t)b * NPIX + i0) * CHALF;
#pragma unroll
    for (int e = 0; e < 8; ++e) {
        int idx = e * 256 + tid;
        int row = idx >> 4, kb = idx & 15;
        *(uint4*)(yb + (size_t)row * CHALF + kb * 8) = *(const uint4*)(Es + row * SROW + kb * 16);
    }
}

// ============================================================
// Kernel 6: out via mma. C[m=o][n=i] = w4[o,c] yb[i,c]; + bias + x residual.
// ============================================================
__global__ __launch_bounds__(256) void out_mma_kernel(
    const float* __restrict__ x, const float* __restrict__ b4, float* __restrict__ out)
{
    extern __shared__ __align__(16) char smem[];
    char* Asm = smem;              // 128 * 272
    char* Bsm = smem + 34816;
    const uint32_t Asb = smem_u32(Asm), Bsb = smem_u32(Bsm);

    const int tid = threadIdx.x, wid = tid >> 5, lane = tid & 31;
    const int i0 = blockIdx.x * 128, o0 = blockIdx.y * 128, b = blockIdx.z;

    const __nv_bfloat16* A = d_w4b + (size_t)o0 * CHALF;
    const __nv_bfloat16* Bt = d_yb + ((size_t)b * NPIX + i0) * CHALF;

#pragma unroll
    for (int e = 0; e < 8; ++e) {
        int idx = e * 256 + tid;
        int row = idx >> 4, kb = idx & 15;
        *(uint4*)(Asm + row * SROW + kb * 16) = *(const uint4*)(A + (size_t)row * CHALF + kb * 8);
        *(uint4*)(Bsm + row * SROW + kb * 16) = *(const uint4*)(Bt + (size_t)row * CHALF + kb * 8);
    }
    __syncthreads();

    const int wm = (wid & 3) * 32, wn = (wid >> 2) * 64;
    const int id = lane >> 3, l7 = lane & 7;

    float acc[2][8][4];
#pragma unroll
    for (int am = 0; am < 2; ++am)
#pragma unroll
        for (int an = 0; an < 8; ++an)
#pragma unroll
            for (int q = 0; q < 4; ++q) acc[am][an][q] = 0.f;

#pragma unroll
    for (int ks = 0; ks < 8; ++ks) {
        uint32_t a[2][4];
#pragma unroll
        for (int am = 0; am < 2; ++am) {
            uint32_t addr = Asb + (uint32_t)(wm + am * 16 + (id & 1) * 8 + l7) * SROW
                          + (uint32_t)(ks * 16 + (id >> 1) * 8) * 2;
            ldm_x4(a[am][0], a[am][1], a[am][2], a[am][3], addr);
        }
        uint32_t bf[8][2];
#pragma unroll
        for (int p = 0; p < 4; ++p) {
            uint32_t r0, r1, r2, r3;
            uint32_t addr = Bsb + (uint32_t)(wn + p * 16 + (id >> 1) * 8 + l7) * SROW
                          + (uint32_t)(ks * 16 + (id & 1) * 8) * 2;
            ldm_x4(r0, r1, r2, r3, addr);
            bf[p * 2][0] = r0; bf[p * 2][1] = r1;
            bf[p * 2 + 1][0] = r2; bf[p * 2 + 1][1] = r3;
        }
#pragma unroll
        for (int am = 0; am < 2; ++am)
#pragma unroll
            for (int an = 0; an < 8; ++an)
                mma_bf16(acc[am][an], a[am], bf[an]);
    }
    __syncthreads();

    // stage fp32 [m][n] (stride 132 floats), then add bias + x and write
    float* Ys = (float*)smem;
    const int gID = lane >> 2, tig = lane & 3;
#pragma unroll
    for (int am = 0; am < 2; ++am)
#pragma unroll
        for (int an = 0; an < 8; ++an) {
            int mm = wm + am * 16 + gID, nn = wn + an * 8 + 2 * tig;
            *(float2*)(Ys + mm * 132 + nn)       = make_float2(acc[am][an][0], acc[am][an][1]);
            *(float2*)(Ys + (mm + 8) * 132 + nn) = make_float2(acc[am][an][2], acc[am][an][3]);
        }
    __syncthreads();

#pragma unroll
    for (int e = 0; e < 16; ++e) {
        int idx = e * 256 + tid;
        int row = idx >> 5, col = (idx & 31) * 4;
        float bias = b4[o0 + row];
        size_t off = ((size_t)b * CDIM + o0 + row) * NPIX + i0 + col;
        float4 v = *(const float4*)(Ys + row * 132 + col);
        float4 xv = *(const float4*)&x[off];
        *(float4*)&out[off] = make_float4(v.x + bias + xv.x, v.y + bias + xv.y,
                                          v.z + bias + xv.z, v.w + bias + xv.w);
    }
}

// ============================================================
extern "C" void kernel_launch(void* const* d_in, const int* in_sizes, int n_in,
                              void* d_out, int out_size)
{
    const float* x  = (const float*)d_in[0];
    const float* w1 = (const float*)d_in[1];
    const float* b1 = (const float*)d_in[2];
    const float* w2 = (const float*)d_in[3];
    const float* b2 = (const float*)d_in[4];
    const float* w3 = (const float*)d_in[5];
    const float* b3 = (const float*)d_in[6];
    const float* w4 = (const float*)d_in[7];
    const float* b4 = (const float*)d_in[8];
    float* out = (float*)d_out;

    const int P_SMEM  = 2 * 128 * PROW;          // 135168
    const int SC_SMEM = 2 * 128 * SROW + 2048;   // 71680
    const int Y_SMEM  = 3 * 2 * 128 * SROW;      // 208896
    const int O_SMEM  = 2 * 128 * SROW;          // 69632
    cudaFuncSetAttribute(proj_mma_kernel,   cudaFuncAttributeMaxDynamicSharedMemorySize, P_SMEM);
    cudaFuncSetAttribute(scores_mma_kernel, cudaFuncAttributeMaxDynamicSharedMemorySize, SC_SMEM);
    cudaFuncSetAttribute(y_mma_kernel,      cudaFuncAttributeMaxDynamicSharedMemorySize, Y_SMEM);
    cudaFuncSetAttribute(out_mma_kernel,    cudaFuncAttributeMaxDynamicSharedMemorySize, O_SMEM);

    wconv_kernel     <<<512, 256>>>(w1, w2, w3, w4);
    xT_kernel        <<<dim3(NPIX / 32, CDIM / 32, BATCH), dim3(32, 8)>>>(x);
    proj_mma_kernel  <<<dim3(NPIX / 128, 3, BATCH), 256, P_SMEM>>>(b1, b2, b3);
    scores_mma_kernel<<<dim3(NPIX / 128, NPIX / 128, BATCH), 256, SC_SMEM>>>();
    den_reduce_kernel<<<dim3(NPIX / 1024, BATCH), 256>>>();
    gscale_kernel    <<<dim3(1024), 256>>>();
    y_mma_kernel     <<<dim3(NPIX / 128, BATCH), 256, Y_SMEM>>>();
    out_mma_kernel   <<<dim3(NPIX / 128, CDIM / 128, BATCH), 256, O_SMEM>>>(x, b4, out);
}

// round 7
// speedup vs baseline: 7.6600x; 1.0325x over previous
#include <cuda_runtime.h>
#include <cuda_fp16.h>
#include <math.h>
#include <stdint.h>

#define BATCH 4
#define CDIM  256
#define CHALF 128
#define NPIX  4096

// ---- scratch (device globals; no dynamic allocation allowed) ----
__device__ __half d_wb [3 * CHALF * CDIM];            // w1|w2|w3 f16 [3][128][256]
__device__ __half d_w4b[CDIM * CHALF];                // w4 f16 [256][128]
__device__ __half d_xT [BATCH * NPIX * CDIM];         // x^T [b][n][c] f16
__device__ __half d_thT[BATCH * NPIX * CHALF];        // theta^T [b][i][c] f16
__device__ __half d_phT[BATCH * NPIX * CHALF];        // phi^T   [b][j][c] f16
__device__ __half d_gu [BATCH * CHALF * NPIX];        // g unscaled [b][c][j] f16
__device__ __half d_gs [BATCH * CHALF * NPIX];        // g*4096/den [b][c][j] f16
__device__ __half d_yb [BATCH * NPIX * CHALF];        // y [b][i][c] f16
__device__ float  d_den [BATCH * NPIX];
__device__ float  d_denp[BATCH * 32 * NPIX];
__device__ __half d_E  [(size_t)BATCH * NPIX * NPIX]; // exp(scores) f16, 128 MB

// ================= helpers =================
__device__ __forceinline__ uint32_t smem_u32(const void* p) {
    uint32_t a;
    asm("{ .reg .u64 t; cvta.to.shared.u64 t, %1; cvt.u32.u64 %0, t; }" : "=r"(a) : "l"(p));
    return a;
}
__device__ __forceinline__ uint32_t pack_f16x2(float lo, float hi) {
    __half2 h = __floats2half2_rn(lo, hi);
    return *(uint32_t*)&h;
}
__device__ __forceinline__ void ldm_x4(uint32_t& r0, uint32_t& r1, uint32_t& r2, uint32_t& r3,
                                       uint32_t addr) {
    asm volatile("ldmatrix.sync.aligned.m8n8.x4.shared.b16 {%0,%1,%2,%3}, [%4];"
                 : "=r"(r0), "=r"(r1), "=r"(r2), "=r"(r3) : "r"(addr));
}
// f16 inputs, f32 accum
__device__ __forceinline__ void mma_f16(float* c, const uint32_t* a, const uint32_t* b) {
    asm volatile(
        "mma.sync.aligned.m16n8k16.row.col.f32.f16.f16.f32 "
        "{%0,%1,%2,%3}, {%4,%5,%6,%7}, {%8,%9}, {%0,%1,%2,%3};"
        : "+f"(c[0]), "+f"(c[1]), "+f"(c[2]), "+f"(c[3])
        : "r"(a[0]), "r"(a[1]), "r"(a[2]), "r"(a[3]), "r"(b[0]), "r"(b[1]));
}
// f16 inputs, f16 accum (2 packed regs)
__device__ __forceinline__ void mma_f16acc(uint32_t* c, const uint32_t* a, const uint32_t* b) {
    asm volatile(
        "mma.sync.aligned.m16n8k16.row.col.f16.f16.f16.f16 "
        "{%0,%1}, {%2,%3,%4,%5}, {%6,%7}, {%0,%1};"
        : "+r"(c[0]), "+r"(c[1])
        : "r"(a[0]), "r"(a[1]), "r"(a[2]), "r"(a[3]), "r"(b[0]), "r"(b[1]));
}
__device__ __forceinline__ void cp16(uint32_t dst, const void* src) {
    asm volatile("cp.async.cg.shared.global [%0], [%1], 16;" :: "r"(dst), "l"(src) : "memory");
}
__device__ __forceinline__ void cp_commit() { asm volatile("cp.async.commit_group;" ::: "memory"); }
__device__ __forceinline__ void cp_wait0()  { asm volatile("cp.async.wait_group 0;" ::: "memory"); }
__device__ __forceinline__ void cp_wait1()  { asm volatile("cp.async.wait_group 1;" ::: "memory"); }

#define SROW 272   // 128 f16 row + 16B pad
#define PROW 528   // 256 f16 row + 16B pad

// ============================================================
// Kernel 0a: weight convert to f16
// ============================================================
__global__ void wconv_kernel(const float* __restrict__ w1, const float* __restrict__ w2,
                             const float* __restrict__ w3, const float* __restrict__ w4)
{
    int idx = blockIdx.x * 256 + threadIdx.x;   // 131072 total
    if (idx < 98304) {
        int sel = idx >> 15, r = idx & 32767;
        const float* W = (sel == 0) ? w1 : (sel == 1) ? w2 : w3;
        d_wb[idx] = __float2half(W[r]);
    } else {
        int r = idx - 98304;
        d_w4b[r] = __float2half(w4[r]);
    }
}

// ============================================================
// Kernel 0b: x transpose-convert: [b][c][n] fp32 -> [b][n][c] f16
// ============================================================
__global__ void xT_kernel(const float* __restrict__ x)
{
    __shared__ float t[32][33];
    const int n0 = blockIdx.x * 32, c0 = blockIdx.y * 32, b = blockIdx.z;
    const float* xb = x + ((size_t)b * CDIM + c0) * NPIX + n0;
    for (int r = threadIdx.y; r < 32; r += 8)
        t[r][threadIdx.x] = xb[(size_t)r * NPIX + threadIdx.x];
    __syncthreads();
    __half* o = d_xT + ((size_t)b * NPIX + n0) * CDIM + c0;
    for (int r = threadIdx.y; r < 32; r += 8)
        o[(size_t)r * CDIM + threadIdx.x] = __float2half(t[threadIdx.x][r]);
}

// ============================================================
// Kernel 1: proj via mma (f16 in, f32 acc). M=128, N=128, K=256.
// sel 0/1 -> thT/phT f16 [n][m]; sel 2 -> gu f16 [m][n].
// ============================================================
__global__ __launch_bounds__(256) void proj_mma_kernel(
    const float* __restrict__ b1, const float* __restrict__ b2, const float* __restrict__ b3)
{
    extern __shared__ __align__(16) char smem[];
    char* Asm = smem;               // 128*528 = 67584
    char* Bsm = smem + 67584;
    const uint32_t Asb = smem_u32(Asm), Bsb = smem_u32(Bsm);

    const int tid = threadIdx.x, wid = tid >> 5, lane = tid & 31;
    const int n0 = blockIdx.x * 128, sel = blockIdx.y, b = blockIdx.z;
    const float* Bv = (sel == 0) ? b1 : (sel == 1) ? b2 : b3;

    const __half* W = d_wb + (size_t)sel * CHALF * CDIM;
    const __half* X = d_xT + ((size_t)b * NPIX + n0) * CDIM;

#pragma unroll
    for (int e = 0; e < 16; ++e) {
        int idx = e * 256 + tid;
        int row = idx >> 5, kb = idx & 31;
        cp16(Asb + row * PROW + kb * 16, W + (size_t)row * CDIM + kb * 8);
        cp16(Bsb + row * PROW + kb * 16, X + (size_t)row * CDIM + kb * 8);
    }
    cp_commit(); cp_wait0();
    __syncthreads();

    const int wm = (wid & 3) * 32, wn = (wid >> 2) * 64;
    const int id = lane >> 3, l7 = lane & 7;

    float acc[2][8][4];
#pragma unroll
    for (int am = 0; am < 2; ++am)
#pragma unroll
        for (int an = 0; an < 8; ++an)
#pragma unroll
            for (int q = 0; q < 4; ++q) acc[am][an][q] = 0.f;

#pragma unroll
    for (int ks = 0; ks < 16; ++ks) {
        uint32_t a[2][4];
#pragma unroll
        for (int am = 0; am < 2; ++am) {
            uint32_t addr = Asb + (uint32_t)(wm + am * 16 + (id & 1) * 8 + l7) * PROW
                          + (uint32_t)(ks * 16 + (id >> 1) * 8) * 2;
            ldm_x4(a[am][0], a[am][1], a[am][2], a[am][3], addr);
        }
        uint32_t bf[8][2];
#pragma unroll
        for (int p = 0; p < 4; ++p) {
            uint32_t r0, r1, r2, r3;
            uint32_t addr = Bsb + (uint32_t)(wn + p * 16 + (id >> 1) * 8 + l7) * PROW
                          + (uint32_t)(ks * 16 + (id & 1) * 8) * 2;
            ldm_x4(r0, r1, r2, r3, addr);
            bf[p * 2][0] = r0; bf[p * 2][1] = r1;
            bf[p * 2 + 1][0] = r2; bf[p * 2 + 1][1] = r3;
        }
#pragma unroll
        for (int am = 0; am < 2; ++am)
#pragma unroll
            for (int an = 0; an < 8; ++an)
                mma_f16(acc[am][an], a[am], bf[an]);
    }
    __syncthreads();

    char* Es = smem;
    const int gID = lane >> 2, tig = lane & 3;

    if (sel < 2) {
        // stage transposed [n][m] f16 (stride 272), bias per m
#pragma unroll
        for (int am = 0; am < 2; ++am) {
            float bias0 = Bv[wm + am * 16 + gID];
            float bias1 = Bv[wm + am * 16 + gID + 8];
            int mm = wm + am * 16 + gID;
#pragma unroll
            for (int an = 0; an < 8; ++an) {
                int nn = wn + an * 8 + 2 * tig;
                *(__half*)(Es + nn * SROW + mm * 2)             = __float2half(acc[am][an][0] + bias0);
                *(__half*)(Es + (nn + 1) * SROW + mm * 2)       = __float2half(acc[am][an][1] + bias0);
                *(__half*)(Es + nn * SROW + (mm + 8) * 2)       = __float2half(acc[am][an][2] + bias1);
                *(__half*)(Es + (nn + 1) * SROW + (mm + 8) * 2) = __float2half(acc[am][an][3] + bias1);
            }
        }
        __syncthreads();
        __half* O = ((sel == 0) ? d_thT : d_phT) + (size_t)b * NPIX * CHALF;
#pragma unroll
        for (int e = 0; e < 8; ++e) {
            int idx = e * 256 + tid;
            int row = idx >> 4, kb = idx & 15;
            *(uint4*)(O + (size_t)(n0 + row) * CHALF + kb * 8) = *(const uint4*)(Es + row * SROW + kb * 16);
        }
    } else {
        // stage [m][n] f16 (stride 272), bias per m
#pragma unroll
        for (int am = 0; am < 2; ++am) {
            float bias0 = Bv[wm + am * 16 + gID];
            float bias1 = Bv[wm + am * 16 + gID + 8];
            int mm = wm + am * 16 + gID;
#pragma unroll
            for (int an = 0; an < 8; ++an) {
                int nn = wn + an * 8 + 2 * tig;
                *(uint32_t*)(Es + mm * SROW + nn * 2)       = pack_f16x2(acc[am][an][0] + bias0, acc[am][an][1] + bias0);
                *(uint32_t*)(Es + (mm + 8) * SROW + nn * 2) = pack_f16x2(acc[am][an][2] + bias1, acc[am][an][3] + bias1);
            }
        }
        __syncthreads();
        __half* O = d_gu + (size_t)b * CHALF * NPIX;
#pragma unroll
        for (int e = 0; e < 8; ++e) {
            int idx = e * 256 + tid;
            int row = idx >> 4, kb = idx & 15;
            *(uint4*)(O + (size_t)row * NPIX + n0 + kb * 8) = *(const uint4*)(Es + row * SROW + kb * 16);
        }
    }
}

// ============================================================
// Kernel 2: scores via mma (f16 in, f16 acc -> 32 acc regs, 3 CTAs/SM).
// CTA tile 128(i) x 128(j), K=128. E -> f16 gmem; col sums via shfl.
// ============================================================
__global__ __launch_bounds__(256, 3) void scores_mma_kernel()
{
    extern __shared__ __align__(16) char smem[];
    char* Asm = smem;              // 128 * 272 = 34816
    char* Bsm = smem + 34816;
    float* sums = (float*)(smem + 69632);   // [4][128] fp32 = 2KB
    const uint32_t Asb = smem_u32(Asm), Bsb = smem_u32(Bsm);

    const int tid = threadIdx.x, wid = tid >> 5, lane = tid & 31;
    const int j0 = blockIdx.x * 128, i0 = blockIdx.y * 128, b = blockIdx.z;

    const __half* Ath = d_thT + ((size_t)b * NPIX + i0) * CHALF;
    const __half* Bph = d_phT + ((size_t)b * NPIX + j0) * CHALF;

#pragma unroll
    for (int e = 0; e < 8; ++e) {
        int idx = e * 256 + tid;
        int row = idx >> 4, kb = idx & 15;
        cp16(Asb + row * SROW + kb * 16, Ath + (size_t)row * CHALF + kb * 8);
        cp16(Bsb + row * SROW + kb * 16, Bph + (size_t)row * CHALF + kb * 8);
    }
    cp_commit(); cp_wait0();
    __syncthreads();

    const int wm = (wid & 3) * 32, wn = (wid >> 2) * 64;
    const int id = lane >> 3, l7 = lane & 7;

    uint32_t acc[2][8][2];   // f16x2 accumulators
#pragma unroll
    for (int am = 0; am < 2; ++am)
#pragma unroll
        for (int an = 0; an < 8; ++an) { acc[am][an][0] = 0u; acc[am][an][1] = 0u; }

#pragma unroll
    for (int ks = 0; ks < 8; ++ks) {
        uint32_t a[2][4];
#pragma unroll
        for (int am = 0; am < 2; ++am) {
            uint32_t addr = Asb + (uint32_t)(wm + am * 16 + (id & 1) * 8 + l7) * SROW
                          + (uint32_t)(ks * 16 + (id >> 1) * 8) * 2;
            ldm_x4(a[am][0], a[am][1], a[am][2], a[am][3], addr);
        }
        uint32_t bf[8][2];
#pragma unroll
        for (int p = 0; p < 4; ++p) {
            uint32_t r0, r1, r2, r3;
            uint32_t addr = Bsb + (uint32_t)(wn + p * 16 + (id >> 1) * 8 + l7) * SROW
                          + (uint32_t)(ks * 16 + (id & 1) * 8) * 2;
            ldm_x4(r0, r1, r2, r3, addr);
            bf[p * 2][0] = r0; bf[p * 2][1] = r1;
            bf[p * 2 + 1][0] = r2; bf[p * 2 + 1][1] = r3;
        }
#pragma unroll
        for (int am = 0; am < 2; ++am)
#pragma unroll
            for (int an = 0; an < 8; ++an)
                mma_f16acc(acc[am][an], a[am], bf[an]);
    }
    __syncthreads();   // tile reads done; reuse smem as staging

    // epilogue: per-fragment exp -> stage f16 E + running column sums
    char* Es = smem;
    const int gID = lane >> 2, tig = lane & 3;
    float s[8][2];
#pragma unroll
    for (int an = 0; an < 8; ++an) { s[an][0] = 0.f; s[an][1] = 0.f; }

#pragma unroll
    for (int am = 0; am < 2; ++am)
#pragma unroll
        for (int an = 0; an < 8; ++an) {
            float2 f0 = __half22float2(*(__half2*)&acc[am][an][0]);
            float2 f1 = __half22float2(*(__half2*)&acc[am][an][1]);
            float e0 = __expf(f0.x), e1 = __expf(f0.y);
            float e2 = __expf(f1.x), e3 = __expf(f1.y);
            int m0 = wm + am * 16, n0 = wn + an * 8 + 2 * tig;
            *(uint32_t*)(Es + (m0 + gID) * SROW + n0 * 2)     = pack_f16x2(e0, e1);
            *(uint32_t*)(Es + (m0 + gID + 8) * SROW + n0 * 2) = pack_f16x2(e2, e3);
            s[an][0] += e0 + e2;
            s[an][1] += e1 + e3;
        }

#pragma unroll
    for (int an = 0; an < 8; ++an) {
        float s0 = s[an][0], s1 = s[an][1];
        s0 += __shfl_xor_sync(0xffffffffu, s0, 4);
        s0 += __shfl_xor_sync(0xffffffffu, s0, 8);
        s0 += __shfl_xor_sync(0xffffffffu, s0, 16);
        s1 += __shfl_xor_sync(0xffffffffu, s1, 4);
        s1 += __shfl_xor_sync(0xffffffffu, s1, 8);
        s1 += __shfl_xor_sync(0xffffffffu, s1, 16);
        if (lane < 4) {
            int col = wn + an * 8 + 2 * lane;
            sums[(wid & 3) * 128 + col]     = s0;
            sums[(wid & 3) * 128 + col + 1] = s1;
        }
    }
    __syncthreads();

    __half* Eb = d_E + ((size_t)b * NPIX + i0) * NPIX + j0;
#pragma unroll
    for (int e = 0; e < 8; ++e) {
        int idx = e * 256 + tid;
        int row = idx >> 4, kb = idx & 15;
        *(uint4*)(Eb + (size_t)row * NPIX + kb * 8) = *(const uint4*)(Es + row * SROW + kb * 16);
    }
    if (tid < 128)
        d_denp[((size_t)b * 32 + blockIdx.y) * NPIX + j0 + tid]
            = sums[tid] + sums[128 + tid] + sums[256 + tid] + sums[384 + tid];
}

// ============================================================
// Kernel 3: den reduce over 32 i-tile partials (deterministic, float4)
// ============================================================
__global__ void den_reduce_kernel()
{
    int j = blockIdx.x * 1024 + threadIdx.x * 4;
    int b = blockIdx.y;
    float4 s = make_float4(0.f, 0.f, 0.f, 0.f);
#pragma unroll
    for (int t = 0; t < 32; ++t) {
        float4 v = *(const float4*)&d_denp[((size_t)b * 32 + t) * NPIX + j];
        s.x += v.x; s.y += v.y; s.z += v.z; s.w += v.w;
    }
    *(float4*)&d_den[b * NPIX + j] = s;
}

// ============================================================
// Kernel 4: gs[b][c][j] = f16(gu[b][c][j] * 4096 / den[j])  (range conditioning)
// ============================================================
__global__ void gscale_kernel()
{
    int idx = blockIdx.x * 256 + threadIdx.x;
    int j  = (idx & (NPIX / 8 - 1)) * 8;
    int c  = (idx >> 9) & (CHALF - 1);
    int b  = idx >> 16;
    size_t off = ((size_t)b * CHALF + c) * NPIX + j;
    uint4 gv = *(const uint4*)(d_gu + off);
    const float* dp = d_den + b * NPIX + j;
    float4 e0 = *(const float4*)&dp[0], e1 = *(const float4*)&dp[4];
    const uint32_t* h = (const uint32_t*)&gv;
    float gf[8];
#pragma unroll
    for (int q = 0; q < 4; ++q) {
        float2 f = __half22float2(*(__half2*)&h[q]);
        gf[2 * q] = f.x; gf[2 * q + 1] = f.y;
    }
    uint4 o;
    o.x = pack_f16x2(gf[0] * 4096.f / e0.x, gf[1] * 4096.f / e0.y);
    o.y = pack_f16x2(gf[2] * 4096.f / e0.z, gf[3] * 4096.f / e0.w);
    o.z = pack_f16x2(gf[4] * 4096.f / e1.x, gf[5] * 4096.f / e1.y);
    o.w = pack_f16x2(gf[6] * 4096.f / e1.z, gf[7] * 4096.f / e1.w);
    *(uint4*)(d_gs + off) = o;
}

// ============================================================
// Kernel 5: y via mma (f16 in, f32 acc). CTA tile 128(i) x 128(c), K=4096
// in 32 chunks of 128, 3-stage cp.async pipeline. y = acc/4096 -> f16 [b][i][c].
// ============================================================
__global__ __launch_bounds__(256) void y_mma_kernel()
{
    extern __shared__ __align__(16) char smem[];
    const uint32_t sb = smem_u32(smem);

    const int tid = threadIdx.x, wid = tid >> 5, lane = tid & 31;
    const int i0 = blockIdx.x * 128, b = blockIdx.y;

    const __half* Ebase = d_E  + ((size_t)b * NPIX + i0) * NPIX;
    const __half* Gbase = d_gs + (size_t)b * CHALF * NPIX;

    const int wm = (wid & 3) * 32, wn = (wid >> 2) * 64;
    const int id = lane >> 3, l7 = lane & 7;

    float acc[2][8][4];
#pragma unroll
    for (int am = 0; am < 2; ++am)
#pragma unroll
        for (int an = 0; an < 8; ++an)
#pragma unroll
            for (int q = 0; q < 4; ++q) acc[am][an][q] = 0.f;

    auto issue_chunk = [&](int c) {
        uint32_t st = sb + (uint32_t)(c % 3) * 69632;
        size_t k0 = (size_t)c * 128;
#pragma unroll
        for (int e = 0; e < 8; ++e) {
            int idx = e * 256 + tid;
            int row = idx >> 4, kb = idx & 15;
            cp16(st + row * SROW + kb * 16,         Ebase + (size_t)row * NPIX + k0 + kb * 8);
            cp16(st + 34816 + row * SROW + kb * 16, Gbase + (size_t)row * NPIX + k0 + kb * 8);
        }
    };

    issue_chunk(0); cp_commit();
    issue_chunk(1); cp_commit();

    for (int c = 0; c < 32; ++c) {
        if (c < 31) cp_wait1(); else cp_wait0();
        __syncthreads();
        if (c + 2 < 32) { issue_chunk(c + 2); cp_commit(); }

        uint32_t Ab = sb + (uint32_t)(c % 3) * 69632;
        uint32_t Bb = Ab + 34816;
#pragma unroll
        for (int ks = 0; ks < 8; ++ks) {
            uint32_t a[2][4];
#pragma unroll
            for (int am = 0; am < 2; ++am) {
                uint32_t addr = Ab + (uint32_t)(wm + am * 16 + (id & 1) * 8 + l7) * SROW
                              + (uint32_t)(ks * 16 + (id >> 1) * 8) * 2;
                ldm_x4(a[am][0], a[am][1], a[am][2], a[am][3], addr);
            }
            uint32_t bf[8][2];
#pragma unroll
            for (int p = 0; p < 4; ++p) {
                uint32_t r0, r1, r2, r3;
                uint32_t addr = Bb + (uint32_t)(wn + p * 16 + (id >> 1) * 8 + l7) * SROW
                              + (uint32_t)(ks * 16 + (id & 1) * 8) * 2;
                ldm_x4(r0, r1, r2, r3, addr);
                bf[p * 2][0] = r0; bf[p * 2][1] = r1;
                bf[p * 2 + 1][0] = r2; bf[p * 2 + 1][1] = r3;
            }
#pragma unroll
            for (int am = 0; am < 2; ++am)
#pragma unroll
                for (int an = 0; an < 8; ++an)
                    mma_f16(acc[am][an], a[am], bf[an]);
        }
    }
    __syncthreads();

    // epilogue: y = acc * (1/4096), stage f16 [m=i][n=c], coalesced store
    const float S = 1.f / 4096.f;
    char* Es = smem;
    const int gID = lane >> 2, tig = lane & 3;
#pragma unroll
    for (int am = 0; am < 2; ++am)
#pragma unroll
        for (int an = 0; an < 8; ++an) {
            int mm = wm + am * 16 + gID, nn = wn + an * 8 + 2 * tig;
            *(uint32_t*)(Es + mm * SROW + nn * 2)       = pack_f16x2(acc[am][an][0] * S, acc[am][an][1] * S);
            *(uint32_t*)(Es + (mm + 8) * SROW + nn * 2) = pack_f16x2(acc[am][an][2] * S, acc[am][an][3] * S);
        }
    __syncthreads();

    __half* yb = d_yb + ((size_t)b * NPIX + i0) * CHALF;
#pragma unroll
    for (int e = 0; e < 8; ++e) {
        int idx = e * 256 + tid;
        int row = idx >> 4, kb = idx & 15;
        *(uint4*)(yb + (size_t)row * CHALF + kb * 8) = *(const uint4*)(Es + row * SROW + kb * 16);
    }
}

// ============================================================
// Kernel 6: out via mma (f16 in, f32 acc). C[m=o][n=i] = w4[o,c] yb[i,c];
// + bias + x residual.
// ============================================================
__global__ __launch_bounds__(256) void out_mma_kernel(
    const float* __restrict__ x, const float* __restrict__ b4, float* __restrict__ out)
{
    extern __shared__ __align__(16) char smem[];
    char* Asm = smem;              // 128 * 272
    char* Bsm = smem + 34816;
    const uint32_t Asb = smem_u32(Asm), Bsb = smem_u32(Bsm);

    const int tid = threadIdx.x, wid = tid >> 5, lane = tid & 31;
    const int i0 = blockIdx.x * 128, o0 = blockIdx.y * 128, b = blockIdx.z;

    const __half* A = d_w4b + (size_t)o0 * CHALF;
    const __half* Bt = d_yb + ((size_t)b * NPIX + i0) * CHALF;

#pragma unroll
    for (int e = 0; e < 8; ++e) {
        int idx = e * 256 + tid;
        int row = idx >> 4, kb = idx & 15;
        cp16(Asb + row * SROW + kb * 16, A + (size_t)row * CHALF + kb * 8);
        cp16(Bsb + row * SROW + kb * 16, Bt + (size_t)row * CHALF + kb * 8);
    }
    cp_commit(); cp_wait0();
    __syncthreads();

    const int wm = (wid & 3) * 32, wn = (wid >> 2) * 64;
    const int id = lane >> 3, l7 = lane & 7;

    float acc[2][8][4];
#pragma unroll
    for (int am = 0; am < 2; ++am)
#pragma unroll
        for (int an = 0; an < 8; ++an)
#pragma unroll
            for (int q = 0; q < 4; ++q) acc[am][an][q] = 0.f;

#pragma unroll
    for (int ks = 0; ks < 8; ++ks) {
        uint32_t a[2][4];
#pragma unroll
        for (int am = 0; am < 2; ++am) {
            uint32_t addr = Asb + (uint32_t)(wm + am * 16 + (id & 1) * 8 + l7) * SROW
                          + (uint32_t)(ks * 16 + (id >> 1) * 8) * 2;
            ldm_x4(a[am][0], a[am][1], a[am][2], a[am][3], addr);
        }
        uint32_t bf[8][2];
#pragma unroll
        for (int p = 0; p < 4; ++p) {
            uint32_t r0, r1, r2, r3;
            uint32_t addr = Bsb + (uint32_t)(wn + p * 16 + (id >> 1) * 8 + l7) * SROW
                          + (uint32_t)(ks * 16 + (id & 1) * 8) * 2;
            ldm_x4(r0, r1, r2, r3, addr);
            bf[p * 2][0] = r0; bf[p * 2][1] = r1;
            bf[p * 2 + 1][0] = r2; bf[p * 2 + 1][1] = r3;
        }
#pragma unroll
        for (int am = 0; am < 2; ++am)
#pragma unroll
            for (int an = 0; an < 8; ++an)
                mma_f16(acc[am][an], a[am], bf[an]);
    }
    __syncthreads();

    float* Ys = (float*)smem;
    const int gID = lane >> 2, tig = lane & 3;
#pragma unroll
    for (int am = 0; am < 2; ++am)
#pragma unroll
        for (int an = 0; an < 8; ++an) {
            int mm = wm + am * 16 + gID, nn = wn + an * 8 + 2 * tig;
            *(float2*)(Ys + mm * 132 + nn)       = make_float2(acc[am][an][0], acc[am][an][1]);
            *(float2*)(Ys + (mm + 8) * 132 + nn) = make_float2(acc[am][an][2], acc[am][an][3]);
        }
    __syncthreads();

#pragma unroll
    for (int e = 0; e < 16; ++e) {
        int idx = e * 256 + tid;
        int row = idx >> 5, col = (idx & 31) * 4;
        float bias = b4[o0 + row];
        size_t off = ((size_t)b * CDIM + o0 + row) * NPIX + i0 + col;
        float4 v = *(const float4*)(Ys + row * 132 + col);
        float4 xv = *(const float4*)&x[off];
        *(float4*)&out[off] = make_float4(v.x + bias + xv.x, v.y + bias + xv.y,
                                          v.z + bias + xv.z, v.w + bias + xv.w);
    }
}

// ============================================================
extern "C" void kernel_launch(void* const* d_in, const int* in_sizes, int n_in,
                              void* d_out, int out_size)
{
    const float* x  = (const float*)d_in[0];
    const float* w1 = (const float*)d_in[1];
    const float* b1 = (const float*)d_in[2];
    const float* w2 = (const float*)d_in[3];
    const float* b2 = (const float*)d_in[4];
    const float* w3 = (const float*)d_in[5];
    const float* b3 = (const float*)d_in[6];
    const float* w4 = (const float*)d_in[7];
    const float* b4 = (const float*)d_in[8];
    float* out = (float*)d_out;

    const int P_SMEM  = 2 * 128 * PROW;          // 135168
    const int SC_SMEM = 2 * 128 * SROW + 2048;   // 71680
    const int Y_SMEM  = 3 * 2 * 128 * SROW;      // 208896
    const int O_SMEM  = 2 * 128 * SROW;          // 69632
    cudaFuncSetAttribute(proj_mma_kernel,   cudaFuncAttributeMaxDynamicSharedMemorySize, P_SMEM);
    cudaFuncSetAttribute(scores_mma_kernel, cudaFuncAttributeMaxDynamicSharedMemorySize, SC_SMEM);
    cudaFuncSetAttribute(y_mma_kernel,      cudaFuncAttributeMaxDynamicSharedMemorySize, Y_SMEM);
    cudaFuncSetAttribute(out_mma_kernel,    cudaFuncAttributeMaxDynamicSharedMemorySize, O_SMEM);

    wconv_kernel     <<<512, 256>>>(w1, w2, w3, w4);
    xT_kernel        <<<dim3(NPIX / 32, CDIM / 32, BATCH), dim3(32, 8)>>>(x);
    proj_mma_kernel  <<<dim3(NPIX / 128, 3, BATCH), 256, P_SMEM>>>(b1, b2, b3);
    scores_mma_kernel<<<dim3(NPIX / 128, NPIX / 128, BATCH), 256, SC_SMEM>>>();
    den_reduce_kernel<<<dim3(NPIX / 1024, BATCH), 256>>>();
    gscale_kernel    <<<dim3(1024), 256>>>();
    y_mma_kernel     <<<dim3(NPIX / 128, BATCH), 256, Y_SMEM>>>();
    out_mma_kernel   <<<dim3(NPIX / 128, CDIM / 128, BATCH), 256, O_SMEM>>>(x, b4, out);
}